// round 1
// baseline (speedup 1.0000x reference)
#include <cuda_runtime.h>
#include <cuda_bf16.h>
#include <math.h>
#include <stdint.h>

// Problem constants
#define NTOK   2048            // B*S
#define SLEN   1024
#define EDIM   1024
#define E4DIM  4096
#define NB     4

// ---------------------------------------------------------------------------
// Scratch (static device globals — allocation-free)
// ---------------------------------------------------------------------------
__device__ float g_h   [NTOK * EDIM];
__device__ float g_t   [NTOK * EDIM];
__device__ float g_t2  [NTOK * EDIM];
__device__ float g_qkv [NTOK * 3 * EDIM];
__device__ float g_a1  [NTOK * EDIM];
__device__ float g_a2  [NTOK * EDIM];
__device__ float g_hid [NTOK * E4DIM];
__device__ float g_mods[2 * 6 * EDIM];
__device__ float g_fmods[2 * 2 * EDIM];
__device__ float g_lam [1];

// ---------------------------------------------------------------------------
// Warp reduce helper
// ---------------------------------------------------------------------------
__device__ __forceinline__ float warp_sum(float v) {
#pragma unroll
    for (int o = 16; o; o >>= 1) v += __shfl_xor_sync(0xffffffffu, v, o);
    return v;
}

// ---------------------------------------------------------------------------
// Tiled SGEMM: C[M,N] = A[M,K] @ W[K,N] (+bias).  BM=BN=128, BK=8, 256 thr,
// 8x8 micro-tile per thread. M assumed multiple of 128; N,K mult of 4/8 with
// N bounds-checked (N=64 case).
// ---------------------------------------------------------------------------
__global__ void __launch_bounds__(256) sgemm_kernel(
    const float* __restrict__ A, const float* __restrict__ W,
    const float* __restrict__ bias, float* __restrict__ C,
    int M, int N, int K)
{
    __shared__ float As[8][128];
    __shared__ float Bs[8][128];

    const int bm = blockIdx.y * 128;
    const int bn = blockIdx.x * 128;
    const int tid = threadIdx.x;
    const int tx = tid & 15;       // 0..15 -> N
    const int ty = tid >> 4;       // 0..15 -> M
    const int arow = tid >> 1;           // 0..127
    const int acol = (tid & 1) * 4;      // 0 or 4
    const int brow = tid >> 5;           // 0..7
    const int bcol = (tid & 31) * 4;     // 0..124

    float acc[8][8];
#pragma unroll
    for (int i = 0; i < 8; i++)
#pragma unroll
        for (int j = 0; j < 8; j++) acc[i][j] = 0.f;

    const float* Aptr = A + (size_t)(bm + arow) * K + acol;
    const float* Wptr = W + (size_t)brow * N + bn + bcol;
    const bool bok = (bn + bcol) < N;

    for (int k0 = 0; k0 < K; k0 += 8) {
        float4 av = *(const float4*)(Aptr + k0);
        As[acol + 0][arow] = av.x;
        As[acol + 1][arow] = av.y;
        As[acol + 2][arow] = av.z;
        As[acol + 3][arow] = av.w;
        float4 bv = bok ? *(const float4*)(Wptr + (size_t)k0 * N)
                        : make_float4(0.f, 0.f, 0.f, 0.f);
        *(float4*)(&Bs[brow][bcol]) = bv;
        __syncthreads();
#pragma unroll
        for (int k = 0; k < 8; k++) {
            float a[8], b[8];
            *(float4*)(a)     = *(const float4*)(&As[k][ty * 8]);
            *(float4*)(a + 4) = *(const float4*)(&As[k][ty * 8 + 4]);
            *(float4*)(b)     = *(const float4*)(&Bs[k][tx * 8]);
            *(float4*)(b + 4) = *(const float4*)(&Bs[k][tx * 8 + 4]);
#pragma unroll
            for (int i = 0; i < 8; i++)
#pragma unroll
                for (int j = 0; j < 8; j++)
                    acc[i][j] += a[i] * b[j];
        }
        __syncthreads();
    }

#pragma unroll
    for (int i = 0; i < 8; i++) {
        size_t row = (size_t)(bm + ty * 8 + i);
#pragma unroll
        for (int j = 0; j < 8; j++) {
            int col = bn + tx * 8 + j;
            if (col < N) {
                float v = acc[i][j];
                if (bias) v += bias[col];
                C[row * N + col] = v;
            }
        }
    }
}

// ---------------------------------------------------------------------------
// Small-M GEMM (M=2): out[2,N] = emb[2,1024] @ W[1024,N] + bias
// ---------------------------------------------------------------------------
__global__ void __launch_bounds__(128) gemm2_kernel(
    const float* __restrict__ A2, const float* __restrict__ W,
    const float* __restrict__ bias, float* __restrict__ out, int N)
{
    int col = blockIdx.x * 128 + threadIdx.x;
    if (col >= N) return;
    float a0 = 0.f, a1 = 0.f;
    const float* wp = W + col;
#pragma unroll 4
    for (int k = 0; k < 1024; k++) {
        float w = __ldg(wp + (size_t)k * N);
        a0 += __ldg(A2 + k) * w;
        a1 += __ldg(A2 + 1024 + k) * w;
    }
    float bv = bias[col];
    out[col]     = a0 + bv;
    out[N + col] = a1 + bv;
}

// ---------------------------------------------------------------------------
// LayerNorm (+ optional affine) + adaLN modulate:
//   y = LN(x)[*w+b] * (1+sc) + sh
// One block per token, 256 threads, 4 elems each.
// ---------------------------------------------------------------------------
template <bool AFF>
__global__ void __launch_bounds__(256) ln_mod_kernel(
    const float* __restrict__ x, const float* __restrict__ w,
    const float* __restrict__ bvec, const float* __restrict__ mods,
    int mstride, int sc_off, int sh_off, float eps, float* __restrict__ out)
{
    __shared__ float red[8];
    const int t = blockIdx.x;
    const int bb = t >> 10;            // batch row (S=1024)
    const int tid = threadIdx.x;
    const float* xr = x + (size_t)t * EDIM;

    float v[4];
    float s = 0.f;
#pragma unroll
    for (int i = 0; i < 4; i++) { v[i] = xr[tid + 256 * i]; s += v[i]; }
    s = warp_sum(s);
    if ((tid & 31) == 0) red[tid >> 5] = s;
    __syncthreads();
    float tot = 0.f;
#pragma unroll
    for (int i = 0; i < 8; i++) tot += red[i];
    float mean = tot * (1.f / 1024.f);
    __syncthreads();

    float q = 0.f;
#pragma unroll
    for (int i = 0; i < 4; i++) { float d = v[i] - mean; q += d * d; }
    q = warp_sum(q);
    if ((tid & 31) == 0) red[tid >> 5] = q;
    __syncthreads();
    float vq = 0.f;
#pragma unroll
    for (int i = 0; i < 8; i++) vq += red[i];
    float inv = rsqrtf(vq * (1.f / 1024.f) + eps);

#pragma unroll
    for (int i = 0; i < 4; i++) {
        int c = tid + 256 * i;
        float y = (v[i] - mean) * inv;
        if (AFF) y = y * w[c] + bvec[c];
        y = y * (1.f + mods[bb * mstride + sc_off + c]) + mods[bb * mstride + sh_off + c];
        out[(size_t)t * EDIM + c] = y;
    }
}

// ---------------------------------------------------------------------------
// Snake activation in place: x += sin(alpha*x)^2 / (beta + 1e-9)
// ---------------------------------------------------------------------------
__global__ void __launch_bounds__(256) snake_kernel(
    float* __restrict__ x, const float* __restrict__ alpha,
    const float* __restrict__ beta, int cmask, int total)
{
    int i = blockIdx.x * 256 + threadIdx.x;
    if (i >= total) return;
    int c = i & cmask;
    float v = x[i];
    float sn = sinf(alpha[c] * v);
    x[i] = v + sn * sn / (beta[c] + 1e-9f);
}

// ---------------------------------------------------------------------------
// Rotary embedding applied in place to q and k halves of qkv.
// q col = h16*64 + d (d<64); rotate first 32 dims: pairs (2j, 2j+1), j<16.
// ---------------------------------------------------------------------------
__global__ void __launch_bounds__(256) rotary_kernel(float* __restrict__ qkv)
{
    int idx = blockIdx.x * 256 + threadIdx.x;   // NTOK*16*16 total
    if (idx >= NTOK * 256) return;
    int t  = idx >> 8;
    int hh = (idx >> 4) & 15;
    int j  = idx & 15;
    int s  = t & (SLEN - 1);
    float inv = powf(10000.f, -(float)(2 * j) * (1.f / 32.f));
    float f = (float)s * inv;
    float sf, cf;
    sincosf(f, &sf, &cf);
    float* qp = qkv + (size_t)t * 3072 + hh * 64 + 2 * j;
    float x1 = qp[0], x2 = qp[1];
    qp[0] = x1 * cf - x2 * sf;
    qp[1] = x2 * cf + x1 * sf;
    float* kp = qp + 1024;
    x1 = kp[0]; x2 = kp[1];
    kp[0] = x1 * cf - x2 * sf;
    kp[1] = x2 * cf + x1 * sf;
}

// ---------------------------------------------------------------------------
// Flash attention (causal, online softmax). One block = 64 query rows for one
// (b, h16) pair; h16 = 2h+sub selects a1 (sub=0) or a2 (sub=1) output.
// smem: Qs[64][68], Ks[64][68], Vs[64][132], Ss[64][65]  (= 85,248 B)
// Thread map: sr=tid>>3 -> rows {sr, sr+32}; sj=tid&7.
//   scores: j = sj + 8*jj (jj<8);  PV/out: cols = sj*4 + 32*cc (cc<4).
// ---------------------------------------------------------------------------
#define FLASH_SMEM ((64*68*2 + 64*132 + 64*65) * 4)

__global__ void __launch_bounds__(256) flash_kernel(
    const float* __restrict__ qkv, float* __restrict__ a1, float* __restrict__ a2)
{
    extern __shared__ float sm[];
    float* Qs = sm;
    float* Ks = sm + 64 * 68;
    float* Vs = sm + 2 * 64 * 68;
    float* Ss = Vs + 64 * 132;

    const int it  = blockIdx.x;    // q tile 0..15
    const int h16 = blockIdx.y;    // 0..15
    const int b   = blockIdx.z;    // 0..1
    const int h   = h16 >> 1;
    const int tid = threadIdx.x;
    const int i0  = it * 64;

    const float* qb = qkv + (size_t)b * SLEN * 3072 + h16 * 64;
    const float* kb = qb + 1024;
    const float* vb = qkv + (size_t)b * SLEN * 3072 + 2048 + h * 128;
    float* ob = ((h16 & 1) ? a2 : a1) + (size_t)b * SLEN * EDIM + h * 128;

    // Load Q tile (64 x 64)
    for (int l = tid; l < 64 * 16; l += 256) {
        int r = l >> 4, c = (l & 15) << 2;
        *(float4*)(Qs + r * 68 + c) = *(const float4*)(qb + (size_t)(i0 + r) * 3072 + c);
    }

    const int sr = tid >> 3;   // 0..31
    const int sj = tid & 7;    // 0..7
    const int cg = sj * 4;     // col base

    float4 acc0[4], acc1[4];
#pragma unroll
    for (int cc = 0; cc < 4; cc++) {
        acc0[cc] = make_float4(0.f, 0.f, 0.f, 0.f);
        acc1[cc] = make_float4(0.f, 0.f, 0.f, 0.f);
    }
    float m0 = -1e30f, m1 = -1e30f, l0 = 0.f, l1 = 0.f;

    __syncthreads();

    for (int jt = 0; jt <= it; jt++) {
        int j0 = jt * 64;
        for (int l = tid; l < 64 * 16; l += 256) {
            int r = l >> 4, c = (l & 15) << 2;
            *(float4*)(Ks + r * 68 + c) = *(const float4*)(kb + (size_t)(j0 + r) * 3072 + c);
        }
        for (int l = tid; l < 64 * 32; l += 256) {
            int r = l >> 5, c = (l & 31) << 2;
            *(float4*)(Vs + r * 132 + c) = *(const float4*)(vb + (size_t)(j0 + r) * 3072 + c);
        }
        __syncthreads();

        // --- scores ---
        float sc0[8], sc1[8];
#pragma unroll
        for (int jj = 0; jj < 8; jj++) { sc0[jj] = 0.f; sc1[jj] = 0.f; }
#pragma unroll
        for (int d = 0; d < 64; d += 4) {
            float4 q0 = *(const float4*)(Qs + sr * 68 + d);
            float4 q1 = *(const float4*)(Qs + (sr + 32) * 68 + d);
#pragma unroll
            for (int jj = 0; jj < 8; jj++) {
                float4 kv = *(const float4*)(Ks + (sj + jj * 8) * 68 + d);
                sc0[jj] += q0.x * kv.x + q0.y * kv.y + q0.z * kv.z + q0.w * kv.w;
                sc1[jj] += q1.x * kv.x + q1.y * kv.y + q1.z * kv.z + q1.w * kv.w;
            }
        }
        // scale + causal mask + row max
        const int row0 = i0 + sr, row1 = i0 + sr + 32;
        float tm0 = -1e30f, tm1 = -1e30f;
#pragma unroll
        for (int jj = 0; jj < 8; jj++) {
            int j = j0 + sj + jj * 8;
            sc0[jj] = (j <= row0) ? sc0[jj] * 0.125f : -1e30f;
            sc1[jj] = (j <= row1) ? sc1[jj] * 0.125f : -1e30f;
            tm0 = fmaxf(tm0, sc0[jj]);
            tm1 = fmaxf(tm1, sc1[jj]);
        }
#pragma unroll
        for (int o = 1; o < 8; o <<= 1) {
            tm0 = fmaxf(tm0, __shfl_xor_sync(0xffffffffu, tm0, o));
            tm1 = fmaxf(tm1, __shfl_xor_sync(0xffffffffu, tm1, o));
        }
        float nm0 = fmaxf(m0, tm0), nm1 = fmaxf(m1, tm1);
        float f0 = __expf(m0 - nm0), f1 = __expf(m1 - nm1);

        float ts0 = 0.f, ts1 = 0.f;
#pragma unroll
        for (int jj = 0; jj < 8; jj++) {
            float p0 = __expf(sc0[jj] - nm0);
            float p1 = __expf(sc1[jj] - nm1);
            ts0 += p0; ts1 += p1;
            Ss[sr * 65 + sj + jj * 8]        = p0;
            Ss[(sr + 32) * 65 + sj + jj * 8] = p1;
        }
#pragma unroll
        for (int o = 1; o < 8; o <<= 1) {
            ts0 += __shfl_xor_sync(0xffffffffu, ts0, o);
            ts1 += __shfl_xor_sync(0xffffffffu, ts1, o);
        }
        l0 = l0 * f0 + ts0;
        l1 = l1 * f1 + ts1;
        m0 = nm0; m1 = nm1;
#pragma unroll
        for (int cc = 0; cc < 4; cc++) {
            acc0[cc].x *= f0; acc0[cc].y *= f0; acc0[cc].z *= f0; acc0[cc].w *= f0;
            acc1[cc].x *= f1; acc1[cc].y *= f1; acc1[cc].z *= f1; acc1[cc].w *= f1;
        }
        __syncwarp();

        // --- PV ---
#pragma unroll 2
        for (int j = 0; j < 64; j++) {
            float p0 = Ss[sr * 65 + j];
            float p1 = Ss[(sr + 32) * 65 + j];
#pragma unroll
            for (int cc = 0; cc < 4; cc++) {
                float4 vv = *(const float4*)(Vs + j * 132 + cg + cc * 32);
                acc0[cc].x += p0 * vv.x; acc0[cc].y += p0 * vv.y;
                acc0[cc].z += p0 * vv.z; acc0[cc].w += p0 * vv.w;
                acc1[cc].x += p1 * vv.x; acc1[cc].y += p1 * vv.y;
                acc1[cc].z += p1 * vv.z; acc1[cc].w += p1 * vv.w;
            }
        }
        __syncthreads();
    }

    float inv0 = 1.f / l0, inv1 = 1.f / l1;
#pragma unroll
    for (int cc = 0; cc < 4; cc++) {
        float4 o0 = acc0[cc], o1 = acc1[cc];
        o0.x *= inv0; o0.y *= inv0; o0.z *= inv0; o0.w *= inv0;
        o1.x *= inv1; o1.y *= inv1; o1.z *= inv1; o1.w *= inv1;
        *(float4*)(ob + (size_t)(i0 + sr) * EDIM + cg + cc * 32)      = o0;
        *(float4*)(ob + (size_t)(i0 + sr + 32) * EDIM + cg + cc * 32) = o1;
    }
}

// ---------------------------------------------------------------------------
// Lambda: lam = exp(sum lq1*lk1) - exp(sum lq2*lk2) + lam_init  (HD=64)
// ---------------------------------------------------------------------------
__global__ void lambda_kernel(const float* __restrict__ lq1, const float* __restrict__ lk1,
                              const float* __restrict__ lq2, const float* __restrict__ lk2,
                              float lam_init, float* __restrict__ out)
{
    int tid = threadIdx.x;   // 32
    float s1 = lq1[tid] * lk1[tid] + lq1[tid + 32] * lk1[tid + 32];
    float s2 = lq2[tid] * lk2[tid] + lq2[tid + 32] * lk2[tid + 32];
    s1 = warp_sum(s1);
    s2 = warp_sum(s2);
    if (tid == 0) out[0] = expf(s1) - expf(s2) + lam_init;
}

// ---------------------------------------------------------------------------
// RMS-norm of (a1 - lam*a2) over last dim 128, *(1-lam_init), into t.
// One block per (token, head), 128 threads.
// ---------------------------------------------------------------------------
__global__ void __launch_bounds__(128) rmsdiff_kernel(
    const float* __restrict__ a1, const float* __restrict__ a2,
    const float* __restrict__ w, const float* __restrict__ bvec,
    const float* __restrict__ lamp, float oml, float* __restrict__ out)
{
    __shared__ float red[4];
    int blk = blockIdx.x;           // token*8 + h
    int tok = blk >> 3, hh = blk & 7;
    int c = threadIdx.x;
    size_t base = (size_t)tok * EDIM + hh * 128 + c;
    float lam = lamp[0];
    float y = a1[base] - lam * a2[base];
    float q = warp_sum(y * y);
    if ((c & 31) == 0) red[c >> 5] = q;
    __syncthreads();
    float tot = red[0] + red[1] + red[2] + red[3];
    float inv = rsqrtf(tot * (1.f / 128.f) + 1e-8f);
    out[base] = (y * inv * w[c] + bvec[c]) * oml;
}

// ---------------------------------------------------------------------------
// Gated residual: h += t2 * sigmoid(1 - g)
// ---------------------------------------------------------------------------
__global__ void __launch_bounds__(256) gate_res_kernel(
    const float* __restrict__ t2, const float* __restrict__ mods,
    int goff, float* __restrict__ h)
{
    int i = blockIdx.x * 256 + threadIdx.x;
    if (i >= NTOK * EDIM) return;
    int bb = i >> 20;          // / (1024*1024)
    int c = i & 1023;
    float g = mods[bb * 6144 + goff + c];
    float sg = 1.f / (1.f + expf(g - 1.f));   // sigmoid(1-g)
    h[i] += t2[i] * sg;
}

// ---------------------------------------------------------------------------
// Launch
// ---------------------------------------------------------------------------
extern "C" void kernel_launch(void* const* d_in, const int* in_sizes, int n_in,
                              void* d_out, int out_size)
{
    const float* x        = (const float*)d_in[0];
    const float* emb      = (const float*)d_in[1];
    const float* l2e_w1   = (const float*)d_in[2];
    const float* l2e_b1   = (const float*)d_in[3];
    const float* l2e_al   = (const float*)d_in[4];
    const float* l2e_be   = (const float*)d_in[5];
    const float* l2e_w2   = (const float*)d_in[6];
    const float* l2e_b2   = (const float*)d_in[7];
    const float* ln1_w    = (const float*)d_in[8];
    const float* ln1_b    = (const float*)d_in[9];
    const float* ln2_w    = (const float*)d_in[10];
    const float* ln2_b    = (const float*)d_in[11];
    const float* qkv_w    = (const float*)d_in[12];
    const float* out_w    = (const float*)d_in[13];
    const float* lq1      = (const float*)d_in[14];
    const float* lk1      = (const float*)d_in[15];
    const float* lq2      = (const float*)d_in[16];
    const float* lk2      = (const float*)d_in[17];
    const float* aln_w    = (const float*)d_in[18];
    const float* aln_b    = (const float*)d_in[19];
    const float* ada_w    = (const float*)d_in[20];
    const float* ada_b    = (const float*)d_in[21];
    const float* ff_w1    = (const float*)d_in[22];
    const float* ff_b1    = (const float*)d_in[23];
    const float* ff_al    = (const float*)d_in[24];
    const float* ff_be    = (const float*)d_in[25];
    const float* ff_w2    = (const float*)d_in[26];
    const float* ff_b2    = (const float*)d_in[27];
    const float* adaf_w   = (const float*)d_in[28];
    const float* adaf_b   = (const float*)d_in[29];
    const float* fin_w    = (const float*)d_in[30];
    const float* fin_b    = (const float*)d_in[31];

    float *h_, *t_, *t2_, *qkv_, *a1_, *a2_, *hid_, *mods_, *fmods_, *lam_;
    cudaGetSymbolAddress((void**)&h_,    g_h);
    cudaGetSymbolAddress((void**)&t_,    g_t);
    cudaGetSymbolAddress((void**)&t2_,   g_t2);
    cudaGetSymbolAddress((void**)&qkv_,  g_qkv);
    cudaGetSymbolAddress((void**)&a1_,   g_a1);
    cudaGetSymbolAddress((void**)&a2_,   g_a2);
    cudaGetSymbolAddress((void**)&hid_,  g_hid);
    cudaGetSymbolAddress((void**)&mods_, g_mods);
    cudaGetSymbolAddress((void**)&fmods_,g_fmods);
    cudaGetSymbolAddress((void**)&lam_,  g_lam);

    cudaFuncSetAttribute(flash_kernel, cudaFuncAttributeMaxDynamicSharedMemorySize,
                         FLASH_SMEM);

    auto gemm = [&](const float* A, const float* W, const float* bias, float* C,
                    int M, int N, int K) {
        dim3 grid((N + 127) / 128, M / 128);
        sgemm_kernel<<<grid, 256>>>(A, W, bias, C, M, N, K);
    };

    // latent -> embedding
    gemm(x, l2e_w1, l2e_b1, t_, NTOK, EDIM, 64);
    snake_kernel<<<(NTOK * EDIM) / 256, 256>>>(t_, l2e_al, l2e_be, 1023, NTOK * EDIM);
    gemm(t_, l2e_w2, l2e_b2, h_, NTOK, EDIM, EDIM);

    for (int i = 0; i < NB; i++) {
        float lam_init = (float)(0.8 - 0.6 * exp(-0.3 * (double)(i + 1)));

        gemm2_kernel<<<6144 / 128, 128>>>(emb, ada_w + (size_t)i * EDIM * 6144,
                                          ada_b + i * 6144, mods_, 6144);
        lambda_kernel<<<1, 32>>>(lq1 + i * 64, lk1 + i * 64, lq2 + i * 64, lk2 + i * 64,
                                 lam_init, lam_);

        // attention half
        ln_mod_kernel<true><<<NTOK, 256>>>(h_, ln1_w + i * EDIM, ln1_b + i * EDIM,
                                           mods_, 6144, 0, 1024, 1e-5f, t_);
        gemm(t_, qkv_w + (size_t)i * EDIM * 3072, nullptr, qkv_, NTOK, 3072, EDIM);
        rotary_kernel<<<NTOK, 256>>>(qkv_);
        flash_kernel<<<dim3(16, 16, 2), 256, FLASH_SMEM>>>(qkv_, a1_, a2_);
        rmsdiff_kernel<<<NTOK * 8, 128>>>(a1_, a2_, aln_w + i * 128, aln_b + i * 128,
                                          lam_, 1.f - lam_init, t_);
        gemm(t_, out_w + (size_t)i * EDIM * EDIM, nullptr, t2_, NTOK, EDIM, EDIM);
        gate_res_kernel<<<(NTOK * EDIM) / 256, 256>>>(t2_, mods_, 4096, h_);

        // MLP half
        ln_mod_kernel<true><<<NTOK, 256>>>(h_, ln2_w + i * EDIM, ln2_b + i * EDIM,
                                           mods_, 6144, 2048, 3072, 1e-5f, t_);
        gemm(t_, ff_w1 + (size_t)i * EDIM * E4DIM, ff_b1 + i * E4DIM, hid_,
             NTOK, E4DIM, EDIM);
        snake_kernel<<<(NTOK * E4DIM) / 256, 256>>>(hid_, ff_al + i * E4DIM,
                                                    ff_be + i * E4DIM, 4095,
                                                    NTOK * E4DIM);
        gemm(hid_, ff_w2 + (size_t)i * E4DIM * EDIM, ff_b2 + i * EDIM, t2_,
             NTOK, EDIM, E4DIM);
        gate_res_kernel<<<(NTOK * EDIM) / 256, 256>>>(t2_, mods_, 5120, h_);
    }

    // final adaLN (no affine, eps=1e-6) + projection
    gemm2_kernel<<<2048 / 128, 128>>>(emb, adaf_w, adaf_b, fmods_, 2048);
    ln_mod_kernel<false><<<NTOK, 256>>>(h_, nullptr, nullptr, fmods_, 2048, 0, 1024,
                                        1e-6f, t_);
    gemm(t_, fin_w, fin_b, (float*)d_out, NTOK, 64, EDIM);
}

// round 2
// speedup vs baseline: 2.2580x; 2.2580x over previous
#include <cuda_runtime.h>
#include <cuda_bf16.h>
#include <math.h>
#include <stdint.h>

// Problem constants
#define NTOK   2048            // B*S
#define SLEN   1024
#define EDIM   1024
#define E4DIM  4096
#define NB     4

// ---------------------------------------------------------------------------
// Scratch (static device globals — allocation-free)
// ---------------------------------------------------------------------------
__device__ float g_h   [NTOK * EDIM];
__device__ float g_t   [NTOK * EDIM];
__device__ float g_t2  [NTOK * EDIM];
__device__ float g_qkv [NTOK * 3 * EDIM];
__device__ float g_a1  [NTOK * EDIM];
__device__ float g_a2  [NTOK * EDIM];
__device__ float g_hid [NTOK * E4DIM];
__device__ float g_mods[2 * 6 * EDIM];
__device__ float g_fmods[2 * 2 * EDIM];
__device__ float g_lam [1];
__device__ float g_part[16 * 2 * 6 * EDIM];   // k-split partials for gemm2

// ---------------------------------------------------------------------------
// Helpers
// ---------------------------------------------------------------------------
__device__ __forceinline__ float warp_sum(float v) {
#pragma unroll
    for (int o = 16; o; o >>= 1) v += __shfl_xor_sync(0xffffffffu, v, o);
    return v;
}

__device__ __forceinline__ float f2tf32(float f) {
    uint32_t r;
    asm("cvt.rna.tf32.f32 %0, %1;" : "=r"(r) : "f"(f));
    return __uint_as_float(r);
}

__device__ __forceinline__ void mma_tf32(
    float* c, const uint32_t* a, const uint32_t* b)
{
    asm volatile(
        "mma.sync.aligned.m16n8k8.row.col.f32.tf32.tf32.f32 "
        "{%0,%1,%2,%3}, {%4,%5,%6,%7}, {%8,%9}, {%0,%1,%2,%3};"
        : "+f"(c[0]), "+f"(c[1]), "+f"(c[2]), "+f"(c[3])
        : "r"(a[0]), "r"(a[1]), "r"(a[2]), "r"(a[3]),
          "r"(b[0]), "r"(b[1]));
}

// ---------------------------------------------------------------------------
// TF32 tensor-core GEMM: C[M,N] = A[M,K] @ W[K,N] (+bias)
// BM=BN=128, BK=16, 256 threads = 8 warps (2x4), warp tile 64x32.
// Smem: A as [m][k] stride 20 (conflict-free frag loads: banks 20g+t),
//       B as [k][n] stride 136 (banks 8t+g).
// M must be multiple of 128, K multiple of 16; N bounds-checked.
// ---------------------------------------------------------------------------
__global__ void __launch_bounds__(256) tgemm_kernel(
    const float* __restrict__ A, const float* __restrict__ W,
    const float* __restrict__ bias, float* __restrict__ C,
    int M, int N, int K)
{
    __shared__ float As[128 * 20];
    __shared__ float Bs[16 * 136];

    const int bm  = blockIdx.y * 128;
    const int bn  = blockIdx.x * 128;
    const int tid = threadIdx.x;
    const int wid = tid >> 5, lane = tid & 31;
    const int g = lane >> 2, t = lane & 3;
    const int wm = (wid >> 2) * 64;     // warp m base (0 or 64)
    const int wn = (wid & 3) * 32;      // warp n base (0,32,64,96)

    float acc[4][4][4];
#pragma unroll
    for (int mt = 0; mt < 4; mt++)
#pragma unroll
        for (int nt = 0; nt < 4; nt++)
#pragma unroll
            for (int r = 0; r < 4; r++) acc[mt][nt][r] = 0.f;

    for (int k0 = 0; k0 < K; k0 += 16) {
        // A tile: 128 x 16 -> As[m][k]
#pragma unroll
        for (int l = tid; l < 512; l += 256) {
            int r = l >> 2, c = (l & 3) * 4;
            float4 v = *(const float4*)(A + (size_t)(bm + r) * K + k0 + c);
            float* p = As + r * 20 + c;
            p[0] = f2tf32(v.x); p[1] = f2tf32(v.y);
            p[2] = f2tf32(v.z); p[3] = f2tf32(v.w);
        }
        // B tile: 16 x 128 -> Bs[k][n]
#pragma unroll
        for (int l = tid; l < 512; l += 256) {
            int r = l >> 5, c = (l & 31) * 4;
            int col = bn + c;
            float4 v = (col < N)
                ? *(const float4*)(W + (size_t)(k0 + r) * N + col)
                : make_float4(0.f, 0.f, 0.f, 0.f);
            float* p = Bs + r * 136 + c;
            p[0] = f2tf32(v.x); p[1] = f2tf32(v.y);
            p[2] = f2tf32(v.z); p[3] = f2tf32(v.w);
        }
        __syncthreads();

#pragma unroll
        for (int ks = 0; ks < 16; ks += 8) {
            uint32_t a[4][4], b[4][2];
#pragma unroll
            for (int mt = 0; mt < 4; mt++) {
                int m0 = wm + mt * 16;
                a[mt][0] = __float_as_uint(As[(m0 + g) * 20 + ks + t]);
                a[mt][1] = __float_as_uint(As[(m0 + 8 + g) * 20 + ks + t]);
                a[mt][2] = __float_as_uint(As[(m0 + g) * 20 + ks + t + 4]);
                a[mt][3] = __float_as_uint(As[(m0 + 8 + g) * 20 + ks + t + 4]);
            }
#pragma unroll
            for (int nt = 0; nt < 4; nt++) {
                int n0 = wn + nt * 8;
                b[nt][0] = __float_as_uint(Bs[(ks + t) * 136 + n0 + g]);
                b[nt][1] = __float_as_uint(Bs[(ks + t + 4) * 136 + n0 + g]);
            }
#pragma unroll
            for (int mt = 0; mt < 4; mt++)
#pragma unroll
                for (int nt = 0; nt < 4; nt++)
                    mma_tf32(acc[mt][nt], a[mt], b[nt]);
        }
        __syncthreads();
    }

    // Epilogue
#pragma unroll
    for (int mt = 0; mt < 4; mt++) {
        int r0 = bm + wm + mt * 16 + g;
#pragma unroll
        for (int nt = 0; nt < 4; nt++) {
            int c0 = bn + wn + nt * 8 + 2 * t;
            if (c0 < N) {
                float b0 = bias ? bias[c0]     : 0.f;
                float b1 = bias ? bias[c0 + 1] : 0.f;
                float2 v0 = make_float2(acc[mt][nt][0] + b0, acc[mt][nt][1] + b1);
                float2 v1 = make_float2(acc[mt][nt][2] + b0, acc[mt][nt][3] + b1);
                *(float2*)(C + (size_t)r0 * N + c0)       = v0;
                *(float2*)(C + (size_t)(r0 + 8) * N + c0) = v1;
            }
        }
    }
}

// ---------------------------------------------------------------------------
// Small-M GEMM (M=2) with deterministic 16-way K split.
// part[(kb*2+row)*N + col] = sum over k in [kb*64, kb*64+64)
// ---------------------------------------------------------------------------
__global__ void __launch_bounds__(128) gemm2_part_kernel(
    const float* __restrict__ A2, const float* __restrict__ W,
    float* __restrict__ part, int N)
{
    int col = blockIdx.x * 128 + threadIdx.x;
    int kb  = blockIdx.y;
    int k0  = kb * 64;
    float a0 = 0.f, a1 = 0.f;
    const float* wp = W + (size_t)k0 * N + col;
#pragma unroll 8
    for (int k = 0; k < 64; k++) {
        float w = __ldg(wp + (size_t)k * N);
        a0 += __ldg(A2 + k0 + k) * w;
        a1 += __ldg(A2 + 1024 + k0 + k) * w;
    }
    part[(size_t)(kb * 2 + 0) * N + col] = a0;
    part[(size_t)(kb * 2 + 1) * N + col] = a1;
}

__global__ void __launch_bounds__(256) gemm2_reduce_kernel(
    const float* __restrict__ part, const float* __restrict__ bias,
    float* __restrict__ out, int N)
{
    int i = blockIdx.x * 256 + threadIdx.x;
    if (i >= 2 * N) return;
    int row = (i >= N) ? 1 : 0;
    int col = i - row * N;
    float s = bias[col];
#pragma unroll
    for (int kb = 0; kb < 16; kb++)
        s += part[(size_t)(kb * 2 + row) * N + col];
    out[(size_t)row * N + col] = s;
}

// ---------------------------------------------------------------------------
// LayerNorm (+ optional affine) + adaLN modulate
// ---------------------------------------------------------------------------
template <bool AFF>
__global__ void __launch_bounds__(256) ln_mod_kernel(
    const float* __restrict__ x, const float* __restrict__ w,
    const float* __restrict__ bvec, const float* __restrict__ mods,
    int mstride, int sc_off, int sh_off, float eps, float* __restrict__ out)
{
    __shared__ float red[8];
    const int t = blockIdx.x;
    const int bb = t >> 10;
    const int tid = threadIdx.x;
    const float* xr = x + (size_t)t * EDIM;

    float v[4];
    float s = 0.f;
#pragma unroll
    for (int i = 0; i < 4; i++) { v[i] = xr[tid + 256 * i]; s += v[i]; }
    s = warp_sum(s);
    if ((tid & 31) == 0) red[tid >> 5] = s;
    __syncthreads();
    float tot = 0.f;
#pragma unroll
    for (int i = 0; i < 8; i++) tot += red[i];
    float mean = tot * (1.f / 1024.f);
    __syncthreads();

    float q = 0.f;
#pragma unroll
    for (int i = 0; i < 4; i++) { float d = v[i] - mean; q += d * d; }
    q = warp_sum(q);
    if ((tid & 31) == 0) red[tid >> 5] = q;
    __syncthreads();
    float vq = 0.f;
#pragma unroll
    for (int i = 0; i < 8; i++) vq += red[i];
    float inv = rsqrtf(vq * (1.f / 1024.f) + eps);

#pragma unroll
    for (int i = 0; i < 4; i++) {
        int c = tid + 256 * i;
        float y = (v[i] - mean) * inv;
        if (AFF) y = y * w[c] + bvec[c];
        y = y * (1.f + mods[bb * mstride + sc_off + c]) + mods[bb * mstride + sh_off + c];
        out[(size_t)t * EDIM + c] = y;
    }
}

// ---------------------------------------------------------------------------
// Snake activation in place
// ---------------------------------------------------------------------------
__global__ void __launch_bounds__(256) snake_kernel(
    float* __restrict__ x, const float* __restrict__ alpha,
    const float* __restrict__ beta, int cmask, int total)
{
    int i = blockIdx.x * 256 + threadIdx.x;
    if (i >= total) return;
    int c = i & cmask;
    float v = x[i];
    float sn = sinf(alpha[c] * v);
    x[i] = v + sn * sn / (beta[c] + 1e-9f);
}

// ---------------------------------------------------------------------------
// Rotary embedding in place on q,k halves of qkv
// ---------------------------------------------------------------------------
__global__ void __launch_bounds__(256) rotary_kernel(float* __restrict__ qkv)
{
    int idx = blockIdx.x * 256 + threadIdx.x;
    if (idx >= NTOK * 256) return;
    int t  = idx >> 8;
    int hh = (idx >> 4) & 15;
    int j  = idx & 15;
    int s  = t & (SLEN - 1);
    float inv = powf(10000.f, -(float)(2 * j) * (1.f / 32.f));
    float f = (float)s * inv;
    float sf, cf;
    sincosf(f, &sf, &cf);
    float* qp = qkv + (size_t)t * 3072 + hh * 64 + 2 * j;
    float x1 = qp[0], x2 = qp[1];
    qp[0] = x1 * cf - x2 * sf;
    qp[1] = x2 * cf + x1 * sf;
    float* kp = qp + 1024;
    x1 = kp[0]; x2 = kp[1];
    kp[0] = x1 * cf - x2 * sf;
    kp[1] = x2 * cf + x1 * sf;
}

// ---------------------------------------------------------------------------
// Flash attention (causal, online softmax), fp32 SIMT
// ---------------------------------------------------------------------------
#define FLASH_SMEM ((64*68*2 + 64*132 + 64*65) * 4)

__global__ void __launch_bounds__(256) flash_kernel(
    const float* __restrict__ qkv, float* __restrict__ a1, float* __restrict__ a2)
{
    extern __shared__ float sm[];
    float* Qs = sm;
    float* Ks = sm + 64 * 68;
    float* Vs = sm + 2 * 64 * 68;
    float* Ss = Vs + 64 * 132;

    const int it  = blockIdx.x;
    const int h16 = blockIdx.y;
    const int b   = blockIdx.z;
    const int h   = h16 >> 1;
    const int tid = threadIdx.x;
    const int i0  = it * 64;

    const float* qb = qkv + (size_t)b * SLEN * 3072 + h16 * 64;
    const float* kb = qb + 1024;
    const float* vb = qkv + (size_t)b * SLEN * 3072 + 2048 + h * 128;
    float* ob = ((h16 & 1) ? a2 : a1) + (size_t)b * SLEN * EDIM + h * 128;

    for (int l = tid; l < 64 * 16; l += 256) {
        int r = l >> 4, c = (l & 15) << 2;
        *(float4*)(Qs + r * 68 + c) = *(const float4*)(qb + (size_t)(i0 + r) * 3072 + c);
    }

    const int sr = tid >> 3;
    const int sj = tid & 7;
    const int cg = sj * 4;

    float4 acc0[4], acc1[4];
#pragma unroll
    for (int cc = 0; cc < 4; cc++) {
        acc0[cc] = make_float4(0.f, 0.f, 0.f, 0.f);
        acc1[cc] = make_float4(0.f, 0.f, 0.f, 0.f);
    }
    float m0 = -1e30f, m1 = -1e30f, l0 = 0.f, l1 = 0.f;

    __syncthreads();

    for (int jt = 0; jt <= it; jt++) {
        int j0 = jt * 64;
        for (int l = tid; l < 64 * 16; l += 256) {
            int r = l >> 4, c = (l & 15) << 2;
            *(float4*)(Ks + r * 68 + c) = *(const float4*)(kb + (size_t)(j0 + r) * 3072 + c);
        }
        for (int l = tid; l < 64 * 32; l += 256) {
            int r = l >> 5, c = (l & 31) << 2;
            *(float4*)(Vs + r * 132 + c) = *(const float4*)(vb + (size_t)(j0 + r) * 3072 + c);
        }
        __syncthreads();

        float sc0[8], sc1[8];
#pragma unroll
        for (int jj = 0; jj < 8; jj++) { sc0[jj] = 0.f; sc1[jj] = 0.f; }
#pragma unroll
        for (int d = 0; d < 64; d += 4) {
            float4 q0 = *(const float4*)(Qs + sr * 68 + d);
            float4 q1 = *(const float4*)(Qs + (sr + 32) * 68 + d);
#pragma unroll
            for (int jj = 0; jj < 8; jj++) {
                float4 kv = *(const float4*)(Ks + (sj + jj * 8) * 68 + d);
                sc0[jj] += q0.x * kv.x + q0.y * kv.y + q0.z * kv.z + q0.w * kv.w;
                sc1[jj] += q1.x * kv.x + q1.y * kv.y + q1.z * kv.z + q1.w * kv.w;
            }
        }
        const int row0 = i0 + sr, row1 = i0 + sr + 32;
        float tm0 = -1e30f, tm1 = -1e30f;
#pragma unroll
        for (int jj = 0; jj < 8; jj++) {
            int j = j0 + sj + jj * 8;
            sc0[jj] = (j <= row0) ? sc0[jj] * 0.125f : -1e30f;
            sc1[jj] = (j <= row1) ? sc1[jj] * 0.125f : -1e30f;
            tm0 = fmaxf(tm0, sc0[jj]);
            tm1 = fmaxf(tm1, sc1[jj]);
        }
#pragma unroll
        for (int o = 1; o < 8; o <<= 1) {
            tm0 = fmaxf(tm0, __shfl_xor_sync(0xffffffffu, tm0, o));
            tm1 = fmaxf(tm1, __shfl_xor_sync(0xffffffffu, tm1, o));
        }
        float nm0 = fmaxf(m0, tm0), nm1 = fmaxf(m1, tm1);
        float f0 = __expf(m0 - nm0), f1 = __expf(m1 - nm1);

        float ts0 = 0.f, ts1 = 0.f;
#pragma unroll
        for (int jj = 0; jj < 8; jj++) {
            float p0 = __expf(sc0[jj] - nm0);
            float p1 = __expf(sc1[jj] - nm1);
            ts0 += p0; ts1 += p1;
            Ss[sr * 65 + sj + jj * 8]        = p0;
            Ss[(sr + 32) * 65 + sj + jj * 8] = p1;
        }
#pragma unroll
        for (int o = 1; o < 8; o <<= 1) {
            ts0 += __shfl_xor_sync(0xffffffffu, ts0, o);
            ts1 += __shfl_xor_sync(0xffffffffu, ts1, o);
        }
        l0 = l0 * f0 + ts0;
        l1 = l1 * f1 + ts1;
        m0 = nm0; m1 = nm1;
#pragma unroll
        for (int cc = 0; cc < 4; cc++) {
            acc0[cc].x *= f0; acc0[cc].y *= f0; acc0[cc].z *= f0; acc0[cc].w *= f0;
            acc1[cc].x *= f1; acc1[cc].y *= f1; acc1[cc].z *= f1; acc1[cc].w *= f1;
        }
        __syncwarp();

#pragma unroll 2
        for (int j = 0; j < 64; j++) {
            float p0 = Ss[sr * 65 + j];
            float p1 = Ss[(sr + 32) * 65 + j];
#pragma unroll
            for (int cc = 0; cc < 4; cc++) {
                float4 vv = *(const float4*)(Vs + j * 132 + cg + cc * 32);
                acc0[cc].x += p0 * vv.x; acc0[cc].y += p0 * vv.y;
                acc0[cc].z += p0 * vv.z; acc0[cc].w += p0 * vv.w;
                acc1[cc].x += p1 * vv.x; acc1[cc].y += p1 * vv.y;
                acc1[cc].z += p1 * vv.z; acc1[cc].w += p1 * vv.w;
            }
        }
        __syncthreads();
    }

    float inv0 = 1.f / l0, inv1 = 1.f / l1;
#pragma unroll
    for (int cc = 0; cc < 4; cc++) {
        float4 o0 = acc0[cc], o1 = acc1[cc];
        o0.x *= inv0; o0.y *= inv0; o0.z *= inv0; o0.w *= inv0;
        o1.x *= inv1; o1.y *= inv1; o1.z *= inv1; o1.w *= inv1;
        *(float4*)(ob + (size_t)(i0 + sr) * EDIM + cg + cc * 32)      = o0;
        *(float4*)(ob + (size_t)(i0 + sr + 32) * EDIM + cg + cc * 32) = o1;
    }
}

// ---------------------------------------------------------------------------
// Lambda scalar
// ---------------------------------------------------------------------------
__global__ void lambda_kernel(const float* __restrict__ lq1, const float* __restrict__ lk1,
                              const float* __restrict__ lq2, const float* __restrict__ lk2,
                              float lam_init, float* __restrict__ out)
{
    int tid = threadIdx.x;
    float s1 = lq1[tid] * lk1[tid] + lq1[tid + 32] * lk1[tid + 32];
    float s2 = lq2[tid] * lk2[tid] + lq2[tid + 32] * lk2[tid + 32];
    s1 = warp_sum(s1);
    s2 = warp_sum(s2);
    if (tid == 0) out[0] = expf(s1) - expf(s2) + lam_init;
}

// ---------------------------------------------------------------------------
// RMS-norm of (a1 - lam*a2) per head dim 128
// ---------------------------------------------------------------------------
__global__ void __launch_bounds__(128) rmsdiff_kernel(
    const float* __restrict__ a1, const float* __restrict__ a2,
    const float* __restrict__ w, const float* __restrict__ bvec,
    const float* __restrict__ lamp, float oml, float* __restrict__ out)
{
    __shared__ float red[4];
    int blk = blockIdx.x;
    int tok = blk >> 3, hh = blk & 7;
    int c = threadIdx.x;
    size_t base = (size_t)tok * EDIM + hh * 128 + c;
    float lam = lamp[0];
    float y = a1[base] - lam * a2[base];
    float q = warp_sum(y * y);
    if ((c & 31) == 0) red[c >> 5] = q;
    __syncthreads();
    float tot = red[0] + red[1] + red[2] + red[3];
    float inv = rsqrtf(tot * (1.f / 128.f) + 1e-8f);
    out[base] = (y * inv * w[c] + bvec[c]) * oml;
}

// ---------------------------------------------------------------------------
// Gated residual
// ---------------------------------------------------------------------------
__global__ void __launch_bounds__(256) gate_res_kernel(
    const float* __restrict__ t2, const float* __restrict__ mods,
    int goff, float* __restrict__ h)
{
    int i = blockIdx.x * 256 + threadIdx.x;
    if (i >= NTOK * EDIM) return;
    int bb = i >> 20;
    int c = i & 1023;
    float g = mods[bb * 6144 + goff + c];
    float sg = 1.f / (1.f + expf(g - 1.f));
    h[i] += t2[i] * sg;
}

// ---------------------------------------------------------------------------
// Launch
// ---------------------------------------------------------------------------
extern "C" void kernel_launch(void* const* d_in, const int* in_sizes, int n_in,
                              void* d_out, int out_size)
{
    const float* x        = (const float*)d_in[0];
    const float* emb      = (const float*)d_in[1];
    const float* l2e_w1   = (const float*)d_in[2];
    const float* l2e_b1   = (const float*)d_in[3];
    const float* l2e_al   = (const float*)d_in[4];
    const float* l2e_be   = (const float*)d_in[5];
    const float* l2e_w2   = (const float*)d_in[6];
    const float* l2e_b2   = (const float*)d_in[7];
    const float* ln1_w    = (const float*)d_in[8];
    const float* ln1_b    = (const float*)d_in[9];
    const float* ln2_w    = (const float*)d_in[10];
    const float* ln2_b    = (const float*)d_in[11];
    const float* qkv_w    = (const float*)d_in[12];
    const float* out_w    = (const float*)d_in[13];
    const float* lq1      = (const float*)d_in[14];
    const float* lk1      = (const float*)d_in[15];
    const float* lq2      = (const float*)d_in[16];
    const float* lk2      = (const float*)d_in[17];
    const float* aln_w    = (const float*)d_in[18];
    const float* aln_b    = (const float*)d_in[19];
    const float* ada_w    = (const float*)d_in[20];
    const float* ada_b    = (const float*)d_in[21];
    const float* ff_w1    = (const float*)d_in[22];
    const float* ff_b1    = (const float*)d_in[23];
    const float* ff_al    = (const float*)d_in[24];
    const float* ff_be    = (const float*)d_in[25];
    const float* ff_w2    = (const float*)d_in[26];
    const float* ff_b2    = (const float*)d_in[27];
    const float* adaf_w   = (const float*)d_in[28];
    const float* adaf_b   = (const float*)d_in[29];
    const float* fin_w    = (const float*)d_in[30];
    const float* fin_b    = (const float*)d_in[31];

    float *h_, *t_, *t2_, *qkv_, *a1_, *a2_, *hid_, *mods_, *fmods_, *lam_, *part_;
    cudaGetSymbolAddress((void**)&h_,    g_h);
    cudaGetSymbolAddress((void**)&t_,    g_t);
    cudaGetSymbolAddress((void**)&t2_,   g_t2);
    cudaGetSymbolAddress((void**)&qkv_,  g_qkv);
    cudaGetSymbolAddress((void**)&a1_,   g_a1);
    cudaGetSymbolAddress((void**)&a2_,   g_a2);
    cudaGetSymbolAddress((void**)&hid_,  g_hid);
    cudaGetSymbolAddress((void**)&mods_, g_mods);
    cudaGetSymbolAddress((void**)&fmods_,g_fmods);
    cudaGetSymbolAddress((void**)&lam_,  g_lam);
    cudaGetSymbolAddress((void**)&part_, g_part);

    cudaFuncSetAttribute(flash_kernel, cudaFuncAttributeMaxDynamicSharedMemorySize,
                         FLASH_SMEM);

    auto gemm = [&](const float* A, const float* W, const float* bias, float* C,
                    int M, int N, int K) {
        dim3 grid((N + 127) / 128, M / 128);
        tgemm_kernel<<<grid, 256>>>(A, W, bias, C, M, N, K);
    };
    auto gemm2 = [&](const float* W, const float* bias, float* out, int N) {
        gemm2_part_kernel<<<dim3(N / 128, 16), 128>>>(emb, W, part_, N);
        gemm2_reduce_kernel<<<(2 * N + 255) / 256, 256>>>(part_, bias, out, N);
    };

    // latent -> embedding
    gemm(x, l2e_w1, l2e_b1, t_, NTOK, EDIM, 64);
    snake_kernel<<<(NTOK * EDIM) / 256, 256>>>(t_, l2e_al, l2e_be, 1023, NTOK * EDIM);
    gemm(t_, l2e_w2, l2e_b2, h_, NTOK, EDIM, EDIM);

    for (int i = 0; i < NB; i++) {
        float lam_init = (float)(0.8 - 0.6 * exp(-0.3 * (double)(i + 1)));

        gemm2(ada_w + (size_t)i * EDIM * 6144, ada_b + i * 6144, mods_, 6144);
        lambda_kernel<<<1, 32>>>(lq1 + i * 64, lk1 + i * 64, lq2 + i * 64, lk2 + i * 64,
                                 lam_init, lam_);

        // attention half
        ln_mod_kernel<true><<<NTOK, 256>>>(h_, ln1_w + i * EDIM, ln1_b + i * EDIM,
                                           mods_, 6144, 0, 1024, 1e-5f, t_);
        gemm(t_, qkv_w + (size_t)i * EDIM * 3072, nullptr, qkv_, NTOK, 3072, EDIM);
        rotary_kernel<<<NTOK, 256>>>(qkv_);
        flash_kernel<<<dim3(16, 16, 2), 256, FLASH_SMEM>>>(qkv_, a1_, a2_);
        rmsdiff_kernel<<<NTOK * 8, 128>>>(a1_, a2_, aln_w + i * 128, aln_b + i * 128,
                                          lam_, 1.f - lam_init, t_);
        gemm(t_, out_w + (size_t)i * EDIM * EDIM, nullptr, t2_, NTOK, EDIM, EDIM);
        gate_res_kernel<<<(NTOK * EDIM) / 256, 256>>>(t2_, mods_, 4096, h_);

        // MLP half
        ln_mod_kernel<true><<<NTOK, 256>>>(h_, ln2_w + i * EDIM, ln2_b + i * EDIM,
                                           mods_, 6144, 2048, 3072, 1e-5f, t_);
        gemm(t_, ff_w1 + (size_t)i * EDIM * E4DIM, ff_b1 + i * E4DIM, hid_,
             NTOK, E4DIM, EDIM);
        snake_kernel<<<(NTOK * E4DIM) / 256, 256>>>(hid_, ff_al + i * E4DIM,
                                                    ff_be + i * E4DIM, 4095,
                                                    NTOK * E4DIM);
        gemm(hid_, ff_w2 + (size_t)i * E4DIM * EDIM, ff_b2 + i * EDIM, t2_,
             NTOK, EDIM, E4DIM);
        gate_res_kernel<<<(NTOK * EDIM) / 256, 256>>>(t2_, mods_, 5120, h_);
    }

    // final adaLN + projection
    gemm2(adaf_w, adaf_b, fmods_, 2048);
    ln_mod_kernel<false><<<NTOK, 256>>>(h_, nullptr, nullptr, fmods_, 2048, 0, 1024,
                                        1e-6f, t_);
    gemm(t_, fin_w, fin_b, (float*)d_out, NTOK, 64, EDIM);
}

// round 3
// speedup vs baseline: 3.7202x; 1.6476x over previous
#include <cuda_runtime.h>
#include <cuda_bf16.h>
#include <math.h>
#include <stdint.h>

#define NTOK   2048
#define SLEN   1024
#define EDIM   1024
#define E4DIM  4096
#define NB     4

// ---------------------------------------------------------------------------
// Scratch
// ---------------------------------------------------------------------------
__device__ float g_h   [NTOK * EDIM];
__device__ float g_t   [NTOK * EDIM];
__device__ float g_t2  [NTOK * EDIM];
__device__ float g_qkv [NTOK * 3 * EDIM];
__device__ float g_a1  [NTOK * EDIM];
__device__ float g_a2  [NTOK * EDIM];
__device__ float g_hid [NTOK * E4DIM];
__device__ float g_mods[2 * 6 * EDIM];
__device__ float g_fmods[2 * 2 * EDIM];
__device__ float g_lam [1];
__device__ float g_part[16 * 2 * 6 * EDIM];

// ---------------------------------------------------------------------------
// Helpers
// ---------------------------------------------------------------------------
__device__ __forceinline__ float warp_sum(float v) {
#pragma unroll
    for (int o = 16; o; o >>= 1) v += __shfl_xor_sync(0xffffffffu, v, o);
    return v;
}

__device__ __forceinline__ float tf32f(float f) {
    uint32_t r;
    asm("cvt.rna.tf32.f32 %0, %1;" : "=r"(r) : "f"(f));
    return __uint_as_float(r);
}
__device__ __forceinline__ uint32_t tf32u(float f) {
    uint32_t r;
    asm("cvt.rna.tf32.f32 %0, %1;" : "=r"(r) : "f"(f));
    return r;
}

__device__ __forceinline__ void mma_tf32(
    float* c, const uint32_t* a, const uint32_t* b)
{
    asm volatile(
        "mma.sync.aligned.m16n8k8.row.col.f32.tf32.tf32.f32 "
        "{%0,%1,%2,%3}, {%4,%5,%6,%7}, {%8,%9}, {%0,%1,%2,%3};"
        : "+f"(c[0]), "+f"(c[1]), "+f"(c[2]), "+f"(c[3])
        : "r"(a[0]), "r"(a[1]), "r"(a[2]), "r"(a[3]),
          "r"(b[0]), "r"(b[1]));
}

__device__ __forceinline__ void cp_async16(float* smem, const float* gmem) {
    uint32_t s = (uint32_t)__cvta_generic_to_shared(smem);
    asm volatile("cp.async.cg.shared.global [%0], [%1], 16;"
                 :: "r"(s), "l"(gmem));
}
__device__ __forceinline__ void cp_async16_pred(float* smem, const float* gmem, bool p) {
    uint32_t s = (uint32_t)__cvta_generic_to_shared(smem);
    int sz = p ? 16 : 0;
    asm volatile("cp.async.cg.shared.global [%0], [%1], 16, %2;"
                 :: "r"(s), "l"(gmem), "r"(sz));
}
#define CP_COMMIT() asm volatile("cp.async.commit_group;")
#define CP_WAIT1()  asm volatile("cp.async.wait_group 1;")

// ---------------------------------------------------------------------------
// TF32 tensor-core GEMM with 3-stage cp.async pipeline.
// C[M,N] = A[M,K] @ W[K,N] (+bias). BM=BN=128, BK=16, 256 thr = 8 warps.
// As[m][k] stride 20, Bs[k][n] stride 136 (both conflict-free for frag loads,
// both 16B-aligned rows for cp.async). Raw fp32 staged; cvt.rna at frag load.
// M % 128 == 0, K % 16 == 0, K/16 >= 2; N bounds-checked.
// ---------------------------------------------------------------------------
#define TG_STAGES 3

__global__ void __launch_bounds__(256) tgemm_kernel(
    const float* __restrict__ A, const float* __restrict__ W,
    const float* __restrict__ bias, float* __restrict__ C,
    int M, int N, int K)
{
    __shared__ float As[TG_STAGES][128 * 20];
    __shared__ float Bs[TG_STAGES][16 * 136];

    const int bm  = blockIdx.y * 128;
    const int bn  = blockIdx.x * 128;
    const int tid = threadIdx.x;
    const int wid = tid >> 5, lane = tid & 31;
    const int g = lane >> 2, t = lane & 3;
    const int wm = (wid >> 2) * 64;
    const int wn = (wid & 3) * 32;

    const int KT = K >> 4;

    auto load_stage = [&](int s, int k0) {
#pragma unroll
        for (int u = 0; u < 2; u++) {
            int l = tid + u * 256;
            int r = l >> 2, c = (l & 3) * 4;
            cp_async16(&As[s][r * 20 + c], A + (size_t)(bm + r) * K + k0 + c);
        }
#pragma unroll
        for (int u = 0; u < 2; u++) {
            int l = tid + u * 256;
            int r = l >> 5, c = (l & 31) * 4;
            int col = bn + c;
            bool ok = col < N;
            cp_async16_pred(&Bs[s][r * 136 + c],
                            W + (size_t)(k0 + r) * N + (ok ? col : 0), ok);
        }
    };

    float acc[4][4][4];
#pragma unroll
    for (int mt = 0; mt < 4; mt++)
#pragma unroll
        for (int nt = 0; nt < 4; nt++)
#pragma unroll
            for (int r = 0; r < 4; r++) acc[mt][nt][r] = 0.f;

    load_stage(0, 0);  CP_COMMIT();
    load_stage(1, 16); CP_COMMIT();

    for (int ki = 0; ki < KT; ki++) {
        CP_WAIT1();
        __syncthreads();
        const int sc = ki % TG_STAGES;
        if (ki + 2 < KT) load_stage((ki + 2) % TG_STAGES, (ki + 2) * 16);
        CP_COMMIT();

#pragma unroll
        for (int ks = 0; ks < 16; ks += 8) {
            uint32_t a[4][4], b[4][2];
#pragma unroll
            for (int mt = 0; mt < 4; mt++) {
                int m0 = wm + mt * 16;
                a[mt][0] = tf32u(As[sc][(m0 + g) * 20 + ks + t]);
                a[mt][1] = tf32u(As[sc][(m0 + 8 + g) * 20 + ks + t]);
                a[mt][2] = tf32u(As[sc][(m0 + g) * 20 + ks + t + 4]);
                a[mt][3] = tf32u(As[sc][(m0 + 8 + g) * 20 + ks + t + 4]);
            }
#pragma unroll
            for (int nt = 0; nt < 4; nt++) {
                int n0 = wn + nt * 8;
                b[nt][0] = tf32u(Bs[sc][(ks + t) * 136 + n0 + g]);
                b[nt][1] = tf32u(Bs[sc][(ks + t + 4) * 136 + n0 + g]);
            }
#pragma unroll
            for (int mt = 0; mt < 4; mt++)
#pragma unroll
                for (int nt = 0; nt < 4; nt++)
                    mma_tf32(acc[mt][nt], a[mt], b[nt]);
        }
        __syncthreads();
    }

#pragma unroll
    for (int mt = 0; mt < 4; mt++) {
        int r0 = bm + wm + mt * 16 + g;
#pragma unroll
        for (int nt = 0; nt < 4; nt++) {
            int c0 = bn + wn + nt * 8 + 2 * t;
            if (c0 < N) {
                float b0 = bias ? bias[c0]     : 0.f;
                float b1 = bias ? bias[c0 + 1] : 0.f;
                float2 v0 = make_float2(acc[mt][nt][0] + b0, acc[mt][nt][1] + b1);
                float2 v1 = make_float2(acc[mt][nt][2] + b0, acc[mt][nt][3] + b1);
                *(float2*)(C + (size_t)r0 * N + c0)       = v0;
                *(float2*)(C + (size_t)(r0 + 8) * N + c0) = v1;
            }
        }
    }
}

// ---------------------------------------------------------------------------
// Small-M GEMM (M=2), 16-way K split, float4 columns
// ---------------------------------------------------------------------------
__global__ void __launch_bounds__(128) gemm2_part_kernel(
    const float* __restrict__ A2, const float* __restrict__ W,
    float* __restrict__ part, int N)
{
    int n4 = N >> 2;
    int c4 = blockIdx.x * 128 + threadIdx.x;
    int kb = blockIdx.y, k0 = kb * 64;
    float4 s0 = make_float4(0.f, 0.f, 0.f, 0.f);
    float4 s1 = make_float4(0.f, 0.f, 0.f, 0.f);
    const float4* wp = (const float4*)W + (size_t)k0 * n4 + c4;
#pragma unroll 8
    for (int k = 0; k < 64; k++) {
        float4 w = __ldg(wp + (size_t)k * n4);
        float x0 = __ldg(A2 + k0 + k);
        float x1 = __ldg(A2 + 1024 + k0 + k);
        s0.x += x0 * w.x; s0.y += x0 * w.y; s0.z += x0 * w.z; s0.w += x0 * w.w;
        s1.x += x1 * w.x; s1.y += x1 * w.y; s1.z += x1 * w.z; s1.w += x1 * w.w;
    }
    ((float4*)part)[(size_t)(kb * 2 + 0) * n4 + c4] = s0;
    ((float4*)part)[(size_t)(kb * 2 + 1) * n4 + c4] = s1;
}

__global__ void __launch_bounds__(256) gemm2_reduce_kernel(
    const float* __restrict__ part, const float* __restrict__ bias,
    float* __restrict__ out, int N)
{
    int n4 = N >> 2;
    int i = blockIdx.x * 256 + threadIdx.x;
    if (i >= 2 * n4) return;
    int row = (i >= n4) ? 1 : 0;
    int c4 = i - row * n4;
    float4 s = ((const float4*)bias)[c4];
#pragma unroll
    for (int kb = 0; kb < 16; kb++) {
        float4 p = ((const float4*)part)[(size_t)(kb * 2 + row) * n4 + c4];
        s.x += p.x; s.y += p.y; s.z += p.z; s.w += p.w;
    }
    ((float4*)out)[(size_t)row * n4 + c4] = s;
}

// ---------------------------------------------------------------------------
// LayerNorm (+ optional affine) + adaLN modulate
// ---------------------------------------------------------------------------
template <bool AFF>
__global__ void __launch_bounds__(256) ln_mod_kernel(
    const float* __restrict__ x, const float* __restrict__ w,
    const float* __restrict__ bvec, const float* __restrict__ mods,
    int mstride, int sc_off, int sh_off, float eps, float* __restrict__ out)
{
    __shared__ float red[8];
    const int t = blockIdx.x;
    const int bb = t >> 10;
    const int tid = threadIdx.x;
    const float* xr = x + (size_t)t * EDIM;

    float v[4];
    float s = 0.f;
#pragma unroll
    for (int i = 0; i < 4; i++) { v[i] = xr[tid + 256 * i]; s += v[i]; }
    s = warp_sum(s);
    if ((tid & 31) == 0) red[tid >> 5] = s;
    __syncthreads();
    float tot = 0.f;
#pragma unroll
    for (int i = 0; i < 8; i++) tot += red[i];
    float mean = tot * (1.f / 1024.f);
    __syncthreads();

    float q = 0.f;
#pragma unroll
    for (int i = 0; i < 4; i++) { float d = v[i] - mean; q += d * d; }
    q = warp_sum(q);
    if ((tid & 31) == 0) red[tid >> 5] = q;
    __syncthreads();
    float vq = 0.f;
#pragma unroll
    for (int i = 0; i < 8; i++) vq += red[i];
    float inv = rsqrtf(vq * (1.f / 1024.f) + eps);

#pragma unroll
    for (int i = 0; i < 4; i++) {
        int c = tid + 256 * i;
        float y = (v[i] - mean) * inv;
        if (AFF) y = y * w[c] + bvec[c];
        y = y * (1.f + mods[bb * mstride + sc_off + c]) + mods[bb * mstride + sh_off + c];
        out[(size_t)t * EDIM + c] = y;
    }
}

// ---------------------------------------------------------------------------
// Snake (fast __sinf; args are small: alpha~1, |x|~O(1))
// ---------------------------------------------------------------------------
__global__ void __launch_bounds__(256) snake_kernel(
    float* __restrict__ x, const float* __restrict__ alpha,
    const float* __restrict__ beta, int cmask, int total)
{
    int i = blockIdx.x * 256 + threadIdx.x;
    if (i >= total) return;
    int c = i & cmask;
    float v = x[i];
    float sn = __sinf(alpha[c] * v);
    x[i] = v + sn * sn / (beta[c] + 1e-9f);
}

// ---------------------------------------------------------------------------
// Rotary in place on q,k
// ---------------------------------------------------------------------------
__global__ void __launch_bounds__(256) rotary_kernel(float* __restrict__ qkv)
{
    int idx = blockIdx.x * 256 + threadIdx.x;
    if (idx >= NTOK * 256) return;
    int t  = idx >> 8;
    int hh = (idx >> 4) & 15;
    int j  = idx & 15;
    int s  = t & (SLEN - 1);
    float inv = exp2f(-(float)(2 * j) * (13.2877123795494f / 32.f));
    float f = (float)s * inv;
    float sf, cf;
    sincosf(f, &sf, &cf);
    float* qp = qkv + (size_t)t * 3072 + hh * 64 + 2 * j;
    float x1 = qp[0], x2 = qp[1];
    qp[0] = x1 * cf - x2 * sf;
    qp[1] = x2 * cf + x1 * sf;
    float* kp = qp + 1024;
    x1 = kp[0]; x2 = kp[1];
    kp[0] = x1 * cf - x2 * sf;
    kp[1] = x2 * cf + x1 * sf;
}

// ---------------------------------------------------------------------------
// Tensor-core flash attention (tf32 mma, causal, online softmax).
// Block = 64 q-rows x one (b,h16); 4 warps, warp owns 16 rows.
// Qs/Ks/Ps stride 68 ([row][d or j]); Vs stride 136 ([j][c]).
// All strides conflict-free for their access patterns (4g+t / 8t+g banks).
// ---------------------------------------------------------------------------
#define FT_SMEM ((64*68 + 64*68 + 64*136 + 64*68) * 4)

__global__ void __launch_bounds__(128) flash_tc_kernel(
    const float* __restrict__ qkv, float* __restrict__ a1, float* __restrict__ a2)
{
    extern __shared__ float sm[];
    float* Qs = sm;              // [64][68]
    float* Ks = Qs + 64 * 68;    // [64][68]
    float* Vs = Ks + 64 * 68;    // [64][136]
    float* Ps = Vs + 64 * 136;   // [64][68]

    const int it  = (int)gridDim.x - 1 - (int)blockIdx.x;  // heavy tiles first
    const int h16 = blockIdx.y;
    const int b   = blockIdx.z;
    const int h   = h16 >> 1;
    const int tid = threadIdx.x;
    const int wid = tid >> 5, lane = tid & 31;
    const int g = lane >> 2, t = lane & 3;
    const int i0 = it * 64;
    const int m0 = wid * 16;

    const float* qb = qkv + (size_t)b * SLEN * 3072 + h16 * 64;
    const float* kb = qb + 1024;
    const float* vb = qkv + (size_t)b * SLEN * 3072 + 2048 + h * 128;
    float* ob = ((h16 & 1) ? a2 : a1) + (size_t)b * SLEN * EDIM + h * 128;

    // Q tile 64x64 -> tf32
    for (int l = tid; l < 64 * 16; l += 128) {
        int r = l >> 4, c = (l & 15) << 2;
        float4 v = *(const float4*)(qb + (size_t)(i0 + r) * 3072 + c);
        float* p = Qs + r * 68 + c;
        p[0] = tf32f(v.x); p[1] = tf32f(v.y); p[2] = tf32f(v.z); p[3] = tf32f(v.w);
    }

    float mrow0 = -1e30f, mrow1 = -1e30f, lrow0 = 0.f, lrow1 = 0.f;
    float oacc[16][4];
#pragma unroll
    for (int nt = 0; nt < 16; nt++)
#pragma unroll
        for (int r = 0; r < 4; r++) oacc[nt][r] = 0.f;

    __syncthreads();

    for (int jt = 0; jt <= it; jt++) {
        int j0 = jt * 64;
        for (int l = tid; l < 64 * 16; l += 128) {
            int r = l >> 4, c = (l & 15) << 2;
            float4 v = *(const float4*)(kb + (size_t)(j0 + r) * 3072 + c);
            float* p = Ks + r * 68 + c;
            p[0] = tf32f(v.x); p[1] = tf32f(v.y); p[2] = tf32f(v.z); p[3] = tf32f(v.w);
        }
        for (int l = tid; l < 64 * 32; l += 128) {
            int r = l >> 5, c = (l & 31) << 2;
            float4 v = *(const float4*)(vb + (size_t)(j0 + r) * 3072 + c);
            float* p = Vs + r * 136 + c;
            p[0] = tf32f(v.x); p[1] = tf32f(v.y); p[2] = tf32f(v.z); p[3] = tf32f(v.w);
        }
        __syncthreads();

        // S = Q K^T  (warp rows m0..m0+15, cols 0..63)
        float sacc[8][4];
#pragma unroll
        for (int nt = 0; nt < 8; nt++)
#pragma unroll
            for (int r = 0; r < 4; r++) sacc[nt][r] = 0.f;

#pragma unroll
        for (int ks = 0; ks < 64; ks += 8) {
            uint32_t af[4];
            af[0] = __float_as_uint(Qs[(m0 + g) * 68 + ks + t]);
            af[1] = __float_as_uint(Qs[(m0 + 8 + g) * 68 + ks + t]);
            af[2] = __float_as_uint(Qs[(m0 + g) * 68 + ks + t + 4]);
            af[3] = __float_as_uint(Qs[(m0 + 8 + g) * 68 + ks + t + 4]);
#pragma unroll
            for (int nt = 0; nt < 8; nt++) {
                uint32_t bf[2];
                bf[0] = __float_as_uint(Ks[(nt * 8 + g) * 68 + ks + t]);
                bf[1] = __float_as_uint(Ks[(nt * 8 + g) * 68 + ks + t + 4]);
                mma_tf32(sacc[nt], af, bf);
            }
        }

        // mask + scale + row max (rows m0+g, m0+8+g; cols per thread 2t,2t+1)
        const int row0 = i0 + m0 + g, row1 = row0 + 8;
        float tm0 = -1e30f, tm1 = -1e30f;
#pragma unroll
        for (int nt = 0; nt < 8; nt++) {
            int c0 = j0 + nt * 8 + 2 * t;
            sacc[nt][0] = (c0     <= row0) ? sacc[nt][0] * 0.125f : -1e30f;
            sacc[nt][1] = (c0 + 1 <= row0) ? sacc[nt][1] * 0.125f : -1e30f;
            sacc[nt][2] = (c0     <= row1) ? sacc[nt][2] * 0.125f : -1e30f;
            sacc[nt][3] = (c0 + 1 <= row1) ? sacc[nt][3] * 0.125f : -1e30f;
            tm0 = fmaxf(tm0, fmaxf(sacc[nt][0], sacc[nt][1]));
            tm1 = fmaxf(tm1, fmaxf(sacc[nt][2], sacc[nt][3]));
        }
        tm0 = fmaxf(tm0, __shfl_xor_sync(0xffffffffu, tm0, 1));
        tm0 = fmaxf(tm0, __shfl_xor_sync(0xffffffffu, tm0, 2));
        tm1 = fmaxf(tm1, __shfl_xor_sync(0xffffffffu, tm1, 1));
        tm1 = fmaxf(tm1, __shfl_xor_sync(0xffffffffu, tm1, 2));

        float nm0 = fmaxf(mrow0, tm0), nm1 = fmaxf(mrow1, tm1);
        float f0 = __expf(mrow0 - nm0), f1 = __expf(mrow1 - nm1);
        mrow0 = nm0; mrow1 = nm1;

        float ts0 = 0.f, ts1 = 0.f;
#pragma unroll
        for (int nt = 0; nt < 8; nt++) {
            float p00 = tf32f(__expf(sacc[nt][0] - nm0));
            float p01 = tf32f(__expf(sacc[nt][1] - nm0));
            float p10 = tf32f(__expf(sacc[nt][2] - nm1));
            float p11 = tf32f(__expf(sacc[nt][3] - nm1));
            ts0 += p00 + p01; ts1 += p10 + p11;
            float* pr0 = Ps + (m0 + g) * 68 + nt * 8 + 2 * t;
            float* pr1 = Ps + (m0 + 8 + g) * 68 + nt * 8 + 2 * t;
            pr0[0] = p00; pr0[1] = p01;
            pr1[0] = p10; pr1[1] = p11;
        }
        ts0 += __shfl_xor_sync(0xffffffffu, ts0, 1);
        ts0 += __shfl_xor_sync(0xffffffffu, ts0, 2);
        ts1 += __shfl_xor_sync(0xffffffffu, ts1, 1);
        ts1 += __shfl_xor_sync(0xffffffffu, ts1, 2);
        lrow0 = lrow0 * f0 + ts0;
        lrow1 = lrow1 * f1 + ts1;

#pragma unroll
        for (int nt = 0; nt < 16; nt++) {
            oacc[nt][0] *= f0; oacc[nt][1] *= f0;
            oacc[nt][2] *= f1; oacc[nt][3] *= f1;
        }
        __syncwarp();   // Ps rows owned by this warp only

        // O += P V  (k = j dim)
#pragma unroll
        for (int ks = 0; ks < 64; ks += 8) {
            uint32_t af[4];
            af[0] = __float_as_uint(Ps[(m0 + g) * 68 + ks + t]);
            af[1] = __float_as_uint(Ps[(m0 + 8 + g) * 68 + ks + t]);
            af[2] = __float_as_uint(Ps[(m0 + g) * 68 + ks + t + 4]);
            af[3] = __float_as_uint(Ps[(m0 + 8 + g) * 68 + ks + t + 4]);
#pragma unroll
            for (int nt = 0; nt < 16; nt++) {
                uint32_t bf[2];
                bf[0] = __float_as_uint(Vs[(ks + t) * 136 + nt * 8 + g]);
                bf[1] = __float_as_uint(Vs[(ks + t + 4) * 136 + nt * 8 + g]);
                mma_tf32(oacc[nt], af, bf);
            }
        }
        __syncthreads();
    }

    float inv0 = 1.f / lrow0, inv1 = 1.f / lrow1;
#pragma unroll
    for (int nt = 0; nt < 16; nt++) {
        int c0 = nt * 8 + 2 * t;
        *(float2*)(ob + (size_t)(i0 + m0 + g) * EDIM + c0) =
            make_float2(oacc[nt][0] * inv0, oacc[nt][1] * inv0);
        *(float2*)(ob + (size_t)(i0 + m0 + 8 + g) * EDIM + c0) =
            make_float2(oacc[nt][2] * inv1, oacc[nt][3] * inv1);
    }
}

// ---------------------------------------------------------------------------
// Lambda scalar
// ---------------------------------------------------------------------------
__global__ void lambda_kernel(const float* __restrict__ lq1, const float* __restrict__ lk1,
                              const float* __restrict__ lq2, const float* __restrict__ lk2,
                              float lam_init, float* __restrict__ out)
{
    int tid = threadIdx.x;
    float s1 = lq1[tid] * lk1[tid] + lq1[tid + 32] * lk1[tid + 32];
    float s2 = lq2[tid] * lk2[tid] + lq2[tid + 32] * lk2[tid + 32];
    s1 = warp_sum(s1);
    s2 = warp_sum(s2);
    if (tid == 0) out[0] = expf(s1) - expf(s2) + lam_init;
}

// ---------------------------------------------------------------------------
// RMS-norm of (a1 - lam*a2) per head dim 128
// ---------------------------------------------------------------------------
__global__ void __launch_bounds__(128) rmsdiff_kernel(
    const float* __restrict__ a1, const float* __restrict__ a2,
    const float* __restrict__ w, const float* __restrict__ bvec,
    const float* __restrict__ lamp, float oml, float* __restrict__ out)
{
    __shared__ float red[4];
    int blk = blockIdx.x;
    int tok = blk >> 3, hh = blk & 7;
    int c = threadIdx.x;
    size_t base = (size_t)tok * EDIM + hh * 128 + c;
    float lam = lamp[0];
    float y = a1[base] - lam * a2[base];
    float q = warp_sum(y * y);
    if ((c & 31) == 0) red[c >> 5] = q;
    __syncthreads();
    float tot = red[0] + red[1] + red[2] + red[3];
    float inv = rsqrtf(tot * (1.f / 128.f) + 1e-8f);
    out[base] = (y * inv * w[c] + bvec[c]) * oml;
}

// ---------------------------------------------------------------------------
// Gated residual
// ---------------------------------------------------------------------------
__global__ void __launch_bounds__(256) gate_res_kernel(
    const float* __restrict__ t2, const float* __restrict__ mods,
    int goff, float* __restrict__ h)
{
    int i = blockIdx.x * 256 + threadIdx.x;
    if (i >= NTOK * EDIM) return;
    int bb = i >> 20;
    int c = i & 1023;
    float g = mods[bb * 6144 + goff + c];
    float sg = 1.f / (1.f + __expf(g - 1.f));
    h[i] += t2[i] * sg;
}

// ---------------------------------------------------------------------------
// Launch
// ---------------------------------------------------------------------------
extern "C" void kernel_launch(void* const* d_in, const int* in_sizes, int n_in,
                              void* d_out, int out_size)
{
    const float* x        = (const float*)d_in[0];
    const float* emb      = (const float*)d_in[1];
    const float* l2e_w1   = (const float*)d_in[2];
    const float* l2e_b1   = (const float*)d_in[3];
    const float* l2e_al   = (const float*)d_in[4];
    const float* l2e_be   = (const float*)d_in[5];
    const float* l2e_w2   = (const float*)d_in[6];
    const float* l2e_b2   = (const float*)d_in[7];
    const float* ln1_w    = (const float*)d_in[8];
    const float* ln1_b    = (const float*)d_in[9];
    const float* ln2_w    = (const float*)d_in[10];
    const float* ln2_b    = (const float*)d_in[11];
    const float* qkv_w    = (const float*)d_in[12];
    const float* out_w    = (const float*)d_in[13];
    const float* lq1      = (const float*)d_in[14];
    const float* lk1      = (const float*)d_in[15];
    const float* lq2      = (const float*)d_in[16];
    const float* lk2      = (const float*)d_in[17];
    const float* aln_w    = (const float*)d_in[18];
    const float* aln_b    = (const float*)d_in[19];
    const float* ada_w    = (const float*)d_in[20];
    const float* ada_b    = (const float*)d_in[21];
    const float* ff_w1    = (const float*)d_in[22];
    const float* ff_b1    = (const float*)d_in[23];
    const float* ff_al    = (const float*)d_in[24];
    const float* ff_be    = (const float*)d_in[25];
    const float* ff_w2    = (const float*)d_in[26];
    const float* ff_b2    = (const float*)d_in[27];
    const float* adaf_w   = (const float*)d_in[28];
    const float* adaf_b   = (const float*)d_in[29];
    const float* fin_w    = (const float*)d_in[30];
    const float* fin_b    = (const float*)d_in[31];

    float *h_, *t_, *t2_, *qkv_, *a1_, *a2_, *hid_, *mods_, *fmods_, *lam_, *part_;
    cudaGetSymbolAddress((void**)&h_,    g_h);
    cudaGetSymbolAddress((void**)&t_,    g_t);
    cudaGetSymbolAddress((void**)&t2_,   g_t2);
    cudaGetSymbolAddress((void**)&qkv_,  g_qkv);
    cudaGetSymbolAddress((void**)&a1_,   g_a1);
    cudaGetSymbolAddress((void**)&a2_,   g_a2);
    cudaGetSymbolAddress((void**)&hid_,  g_hid);
    cudaGetSymbolAddress((void**)&mods_, g_mods);
    cudaGetSymbolAddress((void**)&fmods_,g_fmods);
    cudaGetSymbolAddress((void**)&lam_,  g_lam);
    cudaGetSymbolAddress((void**)&part_, g_part);

    cudaFuncSetAttribute(flash_tc_kernel, cudaFuncAttributeMaxDynamicSharedMemorySize,
                         FT_SMEM);

    auto gemm = [&](const float* A, const float* W, const float* bias, float* C,
                    int M, int N, int K) {
        dim3 grid((N + 127) / 128, M / 128);
        tgemm_kernel<<<grid, 256>>>(A, W, bias, C, M, N, K);
    };
    auto gemm2 = [&](const float* W, const float* bias, float* out, int N) {
        gemm2_part_kernel<<<dim3(N / 512, 16), 128>>>(emb, W, part_, N);
        gemm2_reduce_kernel<<<(2 * (N / 4) + 255) / 256, 256>>>(part_, bias, out, N);
    };

    // latent -> embedding
    gemm(x, l2e_w1, l2e_b1, t_, NTOK, EDIM, 64);
    snake_kernel<<<(NTOK * EDIM) / 256, 256>>>(t_, l2e_al, l2e_be, 1023, NTOK * EDIM);
    gemm(t_, l2e_w2, l2e_b2, h_, NTOK, EDIM, EDIM);

    for (int i = 0; i < NB; i++) {
        float lam_init = (float)(0.8 - 0.6 * exp(-0.3 * (double)(i + 1)));

        gemm2(ada_w + (size_t)i * EDIM * 6144, ada_b + i * 6144, mods_, 6144);
        lambda_kernel<<<1, 32>>>(lq1 + i * 64, lk1 + i * 64, lq2 + i * 64, lk2 + i * 64,
                                 lam_init, lam_);

        // attention half
        ln_mod_kernel<true><<<NTOK, 256>>>(h_, ln1_w + i * EDIM, ln1_b + i * EDIM,
                                           mods_, 6144, 0, 1024, 1e-5f, t_);
        gemm(t_, qkv_w + (size_t)i * EDIM * 3072, nullptr, qkv_, NTOK, 3072, EDIM);
        rotary_kernel<<<NTOK, 256>>>(qkv_);
        flash_tc_kernel<<<dim3(16, 16, 2), 128, FT_SMEM>>>(qkv_, a1_, a2_);
        rmsdiff_kernel<<<NTOK * 8, 128>>>(a1_, a2_, aln_w + i * 128, aln_b + i * 128,
                                          lam_, 1.f - lam_init, t_);
        gemm(t_, out_w + (size_t)i * EDIM * EDIM, nullptr, t2_, NTOK, EDIM, EDIM);
        gate_res_kernel<<<(NTOK * EDIM) / 256, 256>>>(t2_, mods_, 4096, h_);

        // MLP half
        ln_mod_kernel<true><<<NTOK, 256>>>(h_, ln2_w + i * EDIM, ln2_b + i * EDIM,
                                           mods_, 6144, 2048, 3072, 1e-5f, t_);
        gemm(t_, ff_w1 + (size_t)i * EDIM * E4DIM, ff_b1 + i * E4DIM, hid_,
             NTOK, E4DIM, EDIM);
        snake_kernel<<<(NTOK * E4DIM) / 256, 256>>>(hid_, ff_al + i * E4DIM,
                                                    ff_be + i * E4DIM, 4095,
                                                    NTOK * E4DIM);
        gemm(hid_, ff_w2 + (size_t)i * E4DIM * EDIM, ff_b2 + i * EDIM, t2_,
             NTOK, EDIM, E4DIM);
        gate_res_kernel<<<(NTOK * EDIM) / 256, 256>>>(t2_, mods_, 5120, h_);
    }

    // final adaLN + projection
    gemm2(adaf_w, adaf_b, fmods_, 2048);
    ln_mod_kernel<false><<<NTOK, 256>>>(h_, nullptr, nullptr, fmods_, 2048, 0, 1024,
                                        1e-6f, t_);
    gemm(t_, fin_w, fin_b, (float*)d_out, NTOK, 64, EDIM);
}

// round 4
// speedup vs baseline: 3.9745x; 1.0684x over previous
#include <cuda_runtime.h>
#include <cuda_bf16.h>
#include <math.h>
#include <stdint.h>

#define NTOK   2048
#define SLEN   1024
#define EDIM   1024
#define E4DIM  4096
#define NB     4

// ---------------------------------------------------------------------------
// Scratch
// ---------------------------------------------------------------------------
__device__ float g_h   [NTOK * EDIM];
__device__ float g_t   [NTOK * EDIM];
__device__ float g_qkv [NTOK * 3 * EDIM];
__device__ float g_a1  [NTOK * EDIM];
__device__ float g_a2  [NTOK * EDIM];
__device__ float g_hid [NTOK * E4DIM];
__device__ float g_mods[2 * 6 * EDIM];
__device__ float g_fmods[2 * 2 * EDIM];
__device__ float g_lam [1];
__device__ float g_part[64 * 2 * 6 * EDIM];

// ---------------------------------------------------------------------------
// Helpers
// ---------------------------------------------------------------------------
__device__ __forceinline__ float warp_sum(float v) {
#pragma unroll
    for (int o = 16; o; o >>= 1) v += __shfl_xor_sync(0xffffffffu, v, o);
    return v;
}

__device__ __forceinline__ float tf32f(float f) {
    uint32_t r;
    asm("cvt.rna.tf32.f32 %0, %1;" : "=r"(r) : "f"(f));
    return __uint_as_float(r);
}
__device__ __forceinline__ uint32_t tf32u(float f) {
    uint32_t r;
    asm("cvt.rna.tf32.f32 %0, %1;" : "=r"(r) : "f"(f));
    return r;
}

__device__ __forceinline__ void mma_tf32(
    float* c, const uint32_t* a, const uint32_t* b)
{
    asm volatile(
        "mma.sync.aligned.m16n8k8.row.col.f32.tf32.tf32.f32 "
        "{%0,%1,%2,%3}, {%4,%5,%6,%7}, {%8,%9}, {%0,%1,%2,%3};"
        : "+f"(c[0]), "+f"(c[1]), "+f"(c[2]), "+f"(c[3])
        : "r"(a[0]), "r"(a[1]), "r"(a[2]), "r"(a[3]),
          "r"(b[0]), "r"(b[1]));
}

__device__ __forceinline__ void cp_async16(float* smem, const float* gmem) {
    uint32_t s = (uint32_t)__cvta_generic_to_shared(smem);
    asm volatile("cp.async.cg.shared.global [%0], [%1], 16;"
                 :: "r"(s), "l"(gmem));
}
__device__ __forceinline__ void cp_async16_pred(float* smem, const float* gmem, bool p) {
    uint32_t s = (uint32_t)__cvta_generic_to_shared(smem);
    int sz = p ? 16 : 0;
    asm volatile("cp.async.cg.shared.global [%0], [%1], 16, %2;"
                 :: "r"(s), "l"(gmem), "r"(sz));
}
#define CP_COMMIT() asm volatile("cp.async.commit_group;")
#define CP_WAIT1()  asm volatile("cp.async.wait_group 1;")

// ---------------------------------------------------------------------------
// TF32 tensor-core GEMM, BK=32, 2-stage cp.async pipeline, fused epilogues.
// C[M,N] = A[M,K] @ W[K,N] (+bias) [+snake | +gated residual]
// BM=BN=128, 256 thr = 8 warps (2x4), warp tile 64x32.
// As[m][k] stride 36 (banks 4g+t), Bs[k][n] stride 136 (banks 8t+g).
// M % 128 == 0, K % 32 == 0, K >= 64; N bounds-checked.
// MODE: 0 = bias only; 1 = snake(p1=alpha,p2=beta); 2 = gated residual
//       (p1=mods, goff; C is h, read-modify-write).
// ---------------------------------------------------------------------------
#define TG_SMEM ((2 * 128 * 36 + 2 * 32 * 136) * 4)

template <int MODE>
__global__ void __launch_bounds__(256) tgemm_kernel(
    const float* __restrict__ A, const float* __restrict__ W,
    const float* __restrict__ bias, float* __restrict__ C,
    int M, int N, int K,
    const float* __restrict__ p1, const float* __restrict__ p2, int goff)
{
    extern __shared__ float sm[];
    float* As = sm;                  // [2][128*36]
    float* Bs = sm + 2 * 128 * 36;   // [2][32*136]

    const int bm  = blockIdx.y * 128;
    const int bn  = blockIdx.x * 128;
    const int tid = threadIdx.x;
    const int wid = tid >> 5, lane = tid & 31;
    const int g = lane >> 2, t = lane & 3;
    const int wm = (wid >> 2) * 64;
    const int wn = (wid & 3) * 32;

    const int KT = K >> 5;

    auto load_stage = [&](int s, int k0) {
        float* as = As + s * 128 * 36;
        float* bs = Bs + s * 32 * 136;
#pragma unroll
        for (int u = 0; u < 4; u++) {
            int l = tid + u * 256;
            int r = l >> 3, c = (l & 7) * 4;
            cp_async16(as + r * 36 + c, A + (size_t)(bm + r) * K + k0 + c);
        }
#pragma unroll
        for (int u = 0; u < 4; u++) {
            int l = tid + u * 256;
            int r = l >> 5, c = (l & 31) * 4;
            int col = bn + c;
            bool ok = col < N;
            cp_async16_pred(bs + r * 136 + c,
                            W + (size_t)(k0 + r) * N + (ok ? col : 0), ok);
        }
    };

    float acc[4][4][4];
#pragma unroll
    for (int mt = 0; mt < 4; mt++)
#pragma unroll
        for (int nt = 0; nt < 4; nt++)
#pragma unroll
            for (int r = 0; r < 4; r++) acc[mt][nt][r] = 0.f;

    load_stage(0, 0);
    CP_COMMIT();

    for (int ki = 0; ki < KT; ki++) {
        if (ki + 1 < KT) load_stage((ki + 1) & 1, (ki + 1) * 32);
        CP_COMMIT();
        CP_WAIT1();
        __syncthreads();

        const float* as = As + (ki & 1) * 128 * 36;
        const float* bs = Bs + (ki & 1) * 32 * 136;
#pragma unroll
        for (int ks = 0; ks < 32; ks += 8) {
            uint32_t a[4][4], b[4][2];
#pragma unroll
            for (int mt = 0; mt < 4; mt++) {
                int m0 = wm + mt * 16;
                a[mt][0] = tf32u(as[(m0 + g) * 36 + ks + t]);
                a[mt][1] = tf32u(as[(m0 + 8 + g) * 36 + ks + t]);
                a[mt][2] = tf32u(as[(m0 + g) * 36 + ks + t + 4]);
                a[mt][3] = tf32u(as[(m0 + 8 + g) * 36 + ks + t + 4]);
            }
#pragma unroll
            for (int nt = 0; nt < 4; nt++) {
                int n0 = wn + nt * 8;
                b[nt][0] = tf32u(bs[(ks + t) * 136 + n0 + g]);
                b[nt][1] = tf32u(bs[(ks + t + 4) * 136 + n0 + g]);
            }
#pragma unroll
            for (int mt = 0; mt < 4; mt++)
#pragma unroll
                for (int nt = 0; nt < 4; nt++)
                    mma_tf32(acc[mt][nt], a[mt], b[nt]);
        }
        __syncthreads();
    }

#pragma unroll
    for (int mt = 0; mt < 4; mt++) {
        int r0 = bm + wm + mt * 16 + g;
#pragma unroll
        for (int nt = 0; nt < 4; nt++) {
            int c0 = bn + wn + nt * 8 + 2 * t;
            if (c0 < N) {
#pragma unroll
                for (int half = 0; half < 2; half++) {
                    int rr = r0 + half * 8;
#pragma unroll
                    for (int e = 0; e < 2; e++) {
                        int cc = c0 + e;
                        float v = acc[mt][nt][half * 2 + e];
                        if (bias) v += bias[cc];
                        if (MODE == 1) {
                            float sn = __sinf(p1[cc] * v);
                            v += sn * sn / (p2[cc] + 1e-9f);
                        }
                        if (MODE == 2) {
                            int bb = rr >> 10;
                            float gg = p1[bb * 6144 + goff + cc];
                            float sg = 1.f / (1.f + __expf(gg - 1.f));
                            v = C[(size_t)rr * N + cc] + v * sg;
                        }
                        C[(size_t)rr * N + cc] = v;
                    }
                }
            }
        }
    }
}

// ---------------------------------------------------------------------------
// Small-M GEMM (M=2), 64-way K split (K=16 each), float4 columns
// ---------------------------------------------------------------------------
__global__ void __launch_bounds__(128) gemm2_part_kernel(
    const float* __restrict__ A2, const float* __restrict__ W,
    float* __restrict__ part, int N)
{
    int n4 = N >> 2;
    int c4 = blockIdx.x * 128 + threadIdx.x;
    int kb = blockIdx.y, k0 = kb * 16;
    float4 s0 = make_float4(0.f, 0.f, 0.f, 0.f);
    float4 s1 = make_float4(0.f, 0.f, 0.f, 0.f);
    const float4* wp = (const float4*)W + (size_t)k0 * n4 + c4;
#pragma unroll 16
    for (int k = 0; k < 16; k++) {
        float4 w = __ldg(wp + (size_t)k * n4);
        float x0 = __ldg(A2 + k0 + k);
        float x1 = __ldg(A2 + 1024 + k0 + k);
        s0.x += x0 * w.x; s0.y += x0 * w.y; s0.z += x0 * w.z; s0.w += x0 * w.w;
        s1.x += x1 * w.x; s1.y += x1 * w.y; s1.z += x1 * w.z; s1.w += x1 * w.w;
    }
    ((float4*)part)[(size_t)(kb * 2 + 0) * n4 + c4] = s0;
    ((float4*)part)[(size_t)(kb * 2 + 1) * n4 + c4] = s1;
}

__global__ void __launch_bounds__(256) gemm2_reduce_kernel(
    const float* __restrict__ part, const float* __restrict__ bias,
    float* __restrict__ out, int N)
{
    int n4 = N >> 2;
    int i = blockIdx.x * 256 + threadIdx.x;
    if (i >= 2 * n4) return;
    int row = (i >= n4) ? 1 : 0;
    int c4 = i - row * n4;
    float4 s = ((const float4*)bias)[c4];
#pragma unroll 16
    for (int kb = 0; kb < 64; kb++) {
        float4 p = ((const float4*)part)[(size_t)(kb * 2 + row) * n4 + c4];
        s.x += p.x; s.y += p.y; s.z += p.z; s.w += p.w;
    }
    ((float4*)out)[(size_t)row * n4 + c4] = s;
}

// ---------------------------------------------------------------------------
// LayerNorm (+ optional affine) + adaLN modulate
// ---------------------------------------------------------------------------
template <bool AFF>
__global__ void __launch_bounds__(256) ln_mod_kernel(
    const float* __restrict__ x, const float* __restrict__ w,
    const float* __restrict__ bvec, const float* __restrict__ mods,
    int mstride, int sc_off, int sh_off, float eps, float* __restrict__ out)
{
    __shared__ float red[8];
    const int t = blockIdx.x;
    const int bb = t >> 10;
    const int tid = threadIdx.x;
    const float* xr = x + (size_t)t * EDIM;

    float v[4];
    float s = 0.f;
#pragma unroll
    for (int i = 0; i < 4; i++) { v[i] = xr[tid + 256 * i]; s += v[i]; }
    s = warp_sum(s);
    if ((tid & 31) == 0) red[tid >> 5] = s;
    __syncthreads();
    float tot = 0.f;
#pragma unroll
    for (int i = 0; i < 8; i++) tot += red[i];
    float mean = tot * (1.f / 1024.f);
    __syncthreads();

    float q = 0.f;
#pragma unroll
    for (int i = 0; i < 4; i++) { float d = v[i] - mean; q += d * d; }
    q = warp_sum(q);
    if ((tid & 31) == 0) red[tid >> 5] = q;
    __syncthreads();
    float vq = 0.f;
#pragma unroll
    for (int i = 0; i < 8; i++) vq += red[i];
    float inv = rsqrtf(vq * (1.f / 1024.f) + eps);

#pragma unroll
    for (int i = 0; i < 4; i++) {
        int c = tid + 256 * i;
        float y = (v[i] - mean) * inv;
        if (AFF) y = y * w[c] + bvec[c];
        y = y * (1.f + mods[bb * mstride + sc_off + c]) + mods[bb * mstride + sh_off + c];
        out[(size_t)t * EDIM + c] = y;
    }
}

// ---------------------------------------------------------------------------
// Rotary in place on q,k
// ---------------------------------------------------------------------------
__global__ void __launch_bounds__(256) rotary_kernel(float* __restrict__ qkv)
{
    int idx = blockIdx.x * 256 + threadIdx.x;
    if (idx >= NTOK * 256) return;
    int t  = idx >> 8;
    int hh = (idx >> 4) & 15;
    int j  = idx & 15;
    int s  = t & (SLEN - 1);
    float inv = exp2f(-(float)(2 * j) * (13.2877123795494f / 32.f));
    float f = (float)s * inv;
    float sf, cf;
    sincosf(f, &sf, &cf);
    float* qp = qkv + (size_t)t * 3072 + hh * 64 + 2 * j;
    float x1 = qp[0], x2 = qp[1];
    qp[0] = x1 * cf - x2 * sf;
    qp[1] = x2 * cf + x1 * sf;
    float* kp = qp + 1024;
    x1 = kp[0]; x2 = kp[1];
    kp[0] = x1 * cf - x2 * sf;
    kp[1] = x2 * cf + x1 * sf;
}

// ---------------------------------------------------------------------------
// Tensor-core flash attention (tf32 mma, causal, online softmax).
// ---------------------------------------------------------------------------
#define FT_SMEM ((64*68 + 64*68 + 64*136 + 64*68) * 4)

__global__ void __launch_bounds__(128) flash_tc_kernel(
    const float* __restrict__ qkv, float* __restrict__ a1, float* __restrict__ a2)
{
    extern __shared__ float sm[];
    float* Qs = sm;              // [64][68]
    float* Ks = Qs + 64 * 68;    // [64][68]
    float* Vs = Ks + 64 * 68;    // [64][136]
    float* Ps = Vs + 64 * 136;   // [64][68]

    const int it  = (int)gridDim.x - 1 - (int)blockIdx.x;
    const int h16 = blockIdx.y;
    const int b   = blockIdx.z;
    const int h   = h16 >> 1;
    const int tid = threadIdx.x;
    const int wid = tid >> 5, lane = tid & 31;
    const int g = lane >> 2, t = lane & 3;
    const int i0 = it * 64;
    const int m0 = wid * 16;

    const float* qb = qkv + (size_t)b * SLEN * 3072 + h16 * 64;
    const float* kb = qb + 1024;
    const float* vb = qkv + (size_t)b * SLEN * 3072 + 2048 + h * 128;
    float* ob = ((h16 & 1) ? a2 : a1) + (size_t)b * SLEN * EDIM + h * 128;

    for (int l = tid; l < 64 * 16; l += 128) {
        int r = l >> 4, c = (l & 15) << 2;
        float4 v = *(const float4*)(qb + (size_t)(i0 + r) * 3072 + c);
        float* p = Qs + r * 68 + c;
        p[0] = tf32f(v.x); p[1] = tf32f(v.y); p[2] = tf32f(v.z); p[3] = tf32f(v.w);
    }

    float mrow0 = -1e30f, mrow1 = -1e30f, lrow0 = 0.f, lrow1 = 0.f;
    float oacc[16][4];
#pragma unroll
    for (int nt = 0; nt < 16; nt++)
#pragma unroll
        for (int r = 0; r < 4; r++) oacc[nt][r] = 0.f;

    __syncthreads();

    for (int jt = 0; jt <= it; jt++) {
        int j0 = jt * 64;
        for (int l = tid; l < 64 * 16; l += 128) {
            int r = l >> 4, c = (l & 15) << 2;
            float4 v = *(const float4*)(kb + (size_t)(j0 + r) * 3072 + c);
            float* p = Ks + r * 68 + c;
            p[0] = tf32f(v.x); p[1] = tf32f(v.y); p[2] = tf32f(v.z); p[3] = tf32f(v.w);
        }
        for (int l = tid; l < 64 * 32; l += 128) {
            int r = l >> 5, c = (l & 31) << 2;
            float4 v = *(const float4*)(vb + (size_t)(j0 + r) * 3072 + c);
            float* p = Vs + r * 136 + c;
            p[0] = tf32f(v.x); p[1] = tf32f(v.y); p[2] = tf32f(v.z); p[3] = tf32f(v.w);
        }
        __syncthreads();

        float sacc[8][4];
#pragma unroll
        for (int nt = 0; nt < 8; nt++)
#pragma unroll
            for (int r = 0; r < 4; r++) sacc[nt][r] = 0.f;

#pragma unroll
        for (int ks = 0; ks < 64; ks += 8) {
            uint32_t af[4];
            af[0] = __float_as_uint(Qs[(m0 + g) * 68 + ks + t]);
            af[1] = __float_as_uint(Qs[(m0 + 8 + g) * 68 + ks + t]);
            af[2] = __float_as_uint(Qs[(m0 + g) * 68 + ks + t + 4]);
            af[3] = __float_as_uint(Qs[(m0 + 8 + g) * 68 + ks + t + 4]);
#pragma unroll
            for (int nt = 0; nt < 8; nt++) {
                uint32_t bf[2];
                bf[0] = __float_as_uint(Ks[(nt * 8 + g) * 68 + ks + t]);
                bf[1] = __float_as_uint(Ks[(nt * 8 + g) * 68 + ks + t + 4]);
                mma_tf32(sacc[nt], af, bf);
            }
        }

        const int row0 = i0 + m0 + g, row1 = row0 + 8;
        float tm0 = -1e30f, tm1 = -1e30f;
#pragma unroll
        for (int nt = 0; nt < 8; nt++) {
            int c0 = j0 + nt * 8 + 2 * t;
            sacc[nt][0] = (c0     <= row0) ? sacc[nt][0] * 0.125f : -1e30f;
            sacc[nt][1] = (c0 + 1 <= row0) ? sacc[nt][1] * 0.125f : -1e30f;
            sacc[nt][2] = (c0     <= row1) ? sacc[nt][2] * 0.125f : -1e30f;
            sacc[nt][3] = (c0 + 1 <= row1) ? sacc[nt][3] * 0.125f : -1e30f;
            tm0 = fmaxf(tm0, fmaxf(sacc[nt][0], sacc[nt][1]));
            tm1 = fmaxf(tm1, fmaxf(sacc[nt][2], sacc[nt][3]));
        }
        tm0 = fmaxf(tm0, __shfl_xor_sync(0xffffffffu, tm0, 1));
        tm0 = fmaxf(tm0, __shfl_xor_sync(0xffffffffu, tm0, 2));
        tm1 = fmaxf(tm1, __shfl_xor_sync(0xffffffffu, tm1, 1));
        tm1 = fmaxf(tm1, __shfl_xor_sync(0xffffffffu, tm1, 2));

        float nm0 = fmaxf(mrow0, tm0), nm1 = fmaxf(mrow1, tm1);
        float f0 = __expf(mrow0 - nm0), f1 = __expf(mrow1 - nm1);
        mrow0 = nm0; mrow1 = nm1;

        float ts0 = 0.f, ts1 = 0.f;
#pragma unroll
        for (int nt = 0; nt < 8; nt++) {
            float p00 = tf32f(__expf(sacc[nt][0] - nm0));
            float p01 = tf32f(__expf(sacc[nt][1] - nm0));
            float p10 = tf32f(__expf(sacc[nt][2] - nm1));
            float p11 = tf32f(__expf(sacc[nt][3] - nm1));
            ts0 += p00 + p01; ts1 += p10 + p11;
            float* pr0 = Ps + (m0 + g) * 68 + nt * 8 + 2 * t;
            float* pr1 = Ps + (m0 + 8 + g) * 68 + nt * 8 + 2 * t;
            pr0[0] = p00; pr0[1] = p01;
            pr1[0] = p10; pr1[1] = p11;
        }
        ts0 += __shfl_xor_sync(0xffffffffu, ts0, 1);
        ts0 += __shfl_xor_sync(0xffffffffu, ts0, 2);
        ts1 += __shfl_xor_sync(0xffffffffu, ts1, 1);
        ts1 += __shfl_xor_sync(0xffffffffu, ts1, 2);
        lrow0 = lrow0 * f0 + ts0;
        lrow1 = lrow1 * f1 + ts1;

#pragma unroll
        for (int nt = 0; nt < 16; nt++) {
            oacc[nt][0] *= f0; oacc[nt][1] *= f0;
            oacc[nt][2] *= f1; oacc[nt][3] *= f1;
        }
        __syncwarp();

#pragma unroll
        for (int ks = 0; ks < 64; ks += 8) {
            uint32_t af[4];
            af[0] = __float_as_uint(Ps[(m0 + g) * 68 + ks + t]);
            af[1] = __float_as_uint(Ps[(m0 + 8 + g) * 68 + ks + t]);
            af[2] = __float_as_uint(Ps[(m0 + g) * 68 + ks + t + 4]);
            af[3] = __float_as_uint(Ps[(m0 + 8 + g) * 68 + ks + t + 4]);
#pragma unroll
            for (int nt = 0; nt < 16; nt++) {
                uint32_t bf[2];
                bf[0] = __float_as_uint(Vs[(ks + t) * 136 + nt * 8 + g]);
                bf[1] = __float_as_uint(Vs[(ks + t + 4) * 136 + nt * 8 + g]);
                mma_tf32(oacc[nt], af, bf);
            }
        }
        __syncthreads();
    }

    float inv0 = 1.f / lrow0, inv1 = 1.f / lrow1;
#pragma unroll
    for (int nt = 0; nt < 16; nt++) {
        int c0 = nt * 8 + 2 * t;
        *(float2*)(ob + (size_t)(i0 + m0 + g) * EDIM + c0) =
            make_float2(oacc[nt][0] * inv0, oacc[nt][1] * inv0);
        *(float2*)(ob + (size_t)(i0 + m0 + 8 + g) * EDIM + c0) =
            make_float2(oacc[nt][2] * inv1, oacc[nt][3] * inv1);
    }
}

// ---------------------------------------------------------------------------
// Lambda scalar
// ---------------------------------------------------------------------------
__global__ void lambda_kernel(const float* __restrict__ lq1, const float* __restrict__ lk1,
                              const float* __restrict__ lq2, const float* __restrict__ lk2,
                              float lam_init, float* __restrict__ out)
{
    int tid = threadIdx.x;
    float s1 = lq1[tid] * lk1[tid] + lq1[tid + 32] * lk1[tid + 32];
    float s2 = lq2[tid] * lk2[tid] + lq2[tid + 32] * lk2[tid + 32];
    s1 = warp_sum(s1);
    s2 = warp_sum(s2);
    if (tid == 0) out[0] = expf(s1) - expf(s2) + lam_init;
}

// ---------------------------------------------------------------------------
// RMS-norm of (a1 - lam*a2) per head dim 128
// ---------------------------------------------------------------------------
__global__ void __launch_bounds__(128) rmsdiff_kernel(
    const float* __restrict__ a1, const float* __restrict__ a2,
    const float* __restrict__ w, const float* __restrict__ bvec,
    const float* __restrict__ lamp, float oml, float* __restrict__ out)
{
    __shared__ float red[4];
    int blk = blockIdx.x;
    int tok = blk >> 3, hh = blk & 7;
    int c = threadIdx.x;
    size_t base = (size_t)tok * EDIM + hh * 128 + c;
    float lam = lamp[0];
    float y = a1[base] - lam * a2[base];
    float q = warp_sum(y * y);
    if ((c & 31) == 0) red[c >> 5] = q;
    __syncthreads();
    float tot = red[0] + red[1] + red[2] + red[3];
    float inv = rsqrtf(tot * (1.f / 128.f) + 1e-8f);
    out[base] = (y * inv * w[c] + bvec[c]) * oml;
}

// ---------------------------------------------------------------------------
// Launch
// ---------------------------------------------------------------------------
extern "C" void kernel_launch(void* const* d_in, const int* in_sizes, int n_in,
                              void* d_out, int out_size)
{
    const float* x        = (const float*)d_in[0];
    const float* emb      = (const float*)d_in[1];
    const float* l2e_w1   = (const float*)d_in[2];
    const float* l2e_b1   = (const float*)d_in[3];
    const float* l2e_al   = (const float*)d_in[4];
    const float* l2e_be   = (const float*)d_in[5];
    const float* l2e_w2   = (const float*)d_in[6];
    const float* l2e_b2   = (const float*)d_in[7];
    const float* ln1_w    = (const float*)d_in[8];
    const float* ln1_b    = (const float*)d_in[9];
    const float* ln2_w    = (const float*)d_in[10];
    const float* ln2_b    = (const float*)d_in[11];
    const float* qkv_w    = (const float*)d_in[12];
    const float* out_w    = (const float*)d_in[13];
    const float* lq1      = (const float*)d_in[14];
    const float* lk1      = (const float*)d_in[15];
    const float* lq2      = (const float*)d_in[16];
    const float* lk2      = (const float*)d_in[17];
    const float* aln_w    = (const float*)d_in[18];
    const float* aln_b    = (const float*)d_in[19];
    const float* ada_w    = (const float*)d_in[20];
    const float* ada_b    = (const float*)d_in[21];
    const float* ff_w1    = (const float*)d_in[22];
    const float* ff_b1    = (const float*)d_in[23];
    const float* ff_al    = (const float*)d_in[24];
    const float* ff_be    = (const float*)d_in[25];
    const float* ff_w2    = (const float*)d_in[26];
    const float* ff_b2    = (const float*)d_in[27];
    const float* adaf_w   = (const float*)d_in[28];
    const float* adaf_b   = (const float*)d_in[29];
    const float* fin_w    = (const float*)d_in[30];
    const float* fin_b    = (const float*)d_in[31];

    float *h_, *t_, *qkv_, *a1_, *a2_, *hid_, *mods_, *fmods_, *lam_, *part_;
    cudaGetSymbolAddress((void**)&h_,    g_h);
    cudaGetSymbolAddress((void**)&t_,    g_t);
    cudaGetSymbolAddress((void**)&qkv_,  g_qkv);
    cudaGetSymbolAddress((void**)&a1_,   g_a1);
    cudaGetSymbolAddress((void**)&a2_,   g_a2);
    cudaGetSymbolAddress((void**)&hid_,  g_hid);
    cudaGetSymbolAddress((void**)&mods_, g_mods);
    cudaGetSymbolAddress((void**)&fmods_,g_fmods);
    cudaGetSymbolAddress((void**)&lam_,  g_lam);
    cudaGetSymbolAddress((void**)&part_, g_part);

    cudaFuncSetAttribute(flash_tc_kernel, cudaFuncAttributeMaxDynamicSharedMemorySize,
                         FT_SMEM);
    cudaFuncSetAttribute(tgemm_kernel<0>, cudaFuncAttributeMaxDynamicSharedMemorySize,
                         TG_SMEM);
    cudaFuncSetAttribute(tgemm_kernel<1>, cudaFuncAttributeMaxDynamicSharedMemorySize,
                         TG_SMEM);
    cudaFuncSetAttribute(tgemm_kernel<2>, cudaFuncAttributeMaxDynamicSharedMemorySize,
                         TG_SMEM);

    auto gemmN = [&](const float* A, const float* W, const float* bias, float* C,
                     int M, int N, int K) {
        dim3 grid((N + 127) / 128, M / 128);
        tgemm_kernel<0><<<grid, 256, TG_SMEM>>>(A, W, bias, C, M, N, K,
                                                nullptr, nullptr, 0);
    };
    auto gemmS = [&](const float* A, const float* W, const float* bias, float* C,
                     int M, int N, int K, const float* al, const float* be) {
        dim3 grid((N + 127) / 128, M / 128);
        tgemm_kernel<1><<<grid, 256, TG_SMEM>>>(A, W, bias, C, M, N, K, al, be, 0);
    };
    auto gemmG = [&](const float* A, const float* W, const float* bias, float* C,
                     int M, int N, int K, const float* mods, int goff) {
        dim3 grid((N + 127) / 128, M / 128);
        tgemm_kernel<2><<<grid, 256, TG_SMEM>>>(A, W, bias, C, M, N, K,
                                                mods, nullptr, goff);
    };
    auto gemm2 = [&](const float* W, const float* bias, float* out, int N) {
        gemm2_part_kernel<<<dim3(N / 512, 64), 128>>>(emb, W, part_, N);
        gemm2_reduce_kernel<<<(2 * (N / 4) + 255) / 256, 256>>>(part_, bias, out, N);
    };

    // latent -> embedding (snake fused into first GEMM epilogue)
    gemmS(x, l2e_w1, l2e_b1, t_, NTOK, EDIM, 64, l2e_al, l2e_be);
    gemmN(t_, l2e_w2, l2e_b2, h_, NTOK, EDIM, EDIM);

    for (int i = 0; i < NB; i++) {
        float lam_init = (float)(0.8 - 0.6 * exp(-0.3 * (double)(i + 1)));

        gemm2(ada_w + (size_t)i * EDIM * 6144, ada_b + i * 6144, mods_, 6144);
        lambda_kernel<<<1, 32>>>(lq1 + i * 64, lk1 + i * 64, lq2 + i * 64, lk2 + i * 64,
                                 lam_init, lam_);

        // attention half
        ln_mod_kernel<true><<<NTOK, 256>>>(h_, ln1_w + i * EDIM, ln1_b + i * EDIM,
                                           mods_, 6144, 0, 1024, 1e-5f, t_);
        gemmN(t_, qkv_w + (size_t)i * EDIM * 3072, nullptr, qkv_, NTOK, 3072, EDIM);
        rotary_kernel<<<NTOK, 256>>>(qkv_);
        flash_tc_kernel<<<dim3(16, 16, 2), 128, FT_SMEM>>>(qkv_, a1_, a2_);
        rmsdiff_kernel<<<NTOK * 8, 128>>>(a1_, a2_, aln_w + i * 128, aln_b + i * 128,
                                          lam_, 1.f - lam_init, t_);
        gemmG(t_, out_w + (size_t)i * EDIM * EDIM, nullptr, h_, NTOK, EDIM, EDIM,
              mods_, 4096);

        // MLP half
        ln_mod_kernel<true><<<NTOK, 256>>>(h_, ln2_w + i * EDIM, ln2_b + i * EDIM,
                                           mods_, 6144, 2048, 3072, 1e-5f, t_);
        gemmS(t_, ff_w1 + (size_t)i * EDIM * E4DIM, ff_b1 + i * E4DIM, hid_,
              NTOK, E4DIM, EDIM, ff_al + i * E4DIM, ff_be + i * E4DIM);
        gemmG(hid_, ff_w2 + (size_t)i * E4DIM * EDIM, ff_b2 + i * EDIM, h_,
              NTOK, EDIM, E4DIM, mods_, 5120);
    }

    // final adaLN + projection
    gemm2(adaf_w, adaf_b, fmods_, 2048);
    ln_mod_kernel<false><<<NTOK, 256>>>(h_, nullptr, nullptr, fmods_, 2048, 0, 1024,
                                        1e-6f, t_);
    gemmN(t_, fin_w, fin_b, (float*)d_out, NTOK, 64, EDIM);
}

// round 5
// speedup vs baseline: 4.0947x; 1.0302x over previous
#include <cuda_runtime.h>
#include <cuda_bf16.h>
#include <math.h>
#include <stdint.h>

#define NTOK   2048
#define SLEN   1024
#define EDIM   1024
#define E4DIM  4096
#define NB     4

// ---------------------------------------------------------------------------
// Scratch
// ---------------------------------------------------------------------------
__device__ float g_h   [NTOK * EDIM];
__device__ float g_t   [NTOK * EDIM];
__device__ float g_qkv [NTOK * 3 * EDIM];
__device__ float g_a1  [NTOK * EDIM];
__device__ float g_a2  [NTOK * EDIM];
__device__ float g_hid [NTOK * E4DIM];
__device__ float g_mods[2 * 6 * EDIM];
__device__ float g_fmods[2 * 2 * EDIM];
__device__ float g_lam [1];
__device__ float g_part[64 * 2 * 6 * EDIM];

// tf32-pre-rounded weights
__device__ float g_w_l2e1[64 * EDIM];
__device__ float g_w_l2e2[EDIM * EDIM];
__device__ float g_w_qkv [NB * EDIM * 3 * EDIM];
__device__ float g_w_out [NB * EDIM * EDIM];
__device__ float g_w_ff1 [NB * EDIM * E4DIM];
__device__ float g_w_ff2 [NB * E4DIM * EDIM];
__device__ float g_w_fin [EDIM * 64];

// ---------------------------------------------------------------------------
// Helpers
// ---------------------------------------------------------------------------
__device__ __forceinline__ float warp_sum(float v) {
#pragma unroll
    for (int o = 16; o; o >>= 1) v += __shfl_xor_sync(0xffffffffu, v, o);
    return v;
}

__device__ __forceinline__ float tf32f(float f) {
    uint32_t r;
    asm("cvt.rna.tf32.f32 %0, %1;" : "=r"(r) : "f"(f));
    return __uint_as_float(r);
}
__device__ __forceinline__ uint32_t tf32u(float f) {
    uint32_t r;
    asm("cvt.rna.tf32.f32 %0, %1;" : "=r"(r) : "f"(f));
    return r;
}

__device__ __forceinline__ void mma_tf32(
    float* c, const uint32_t* a, const uint32_t* b)
{
    asm volatile(
        "mma.sync.aligned.m16n8k8.row.col.f32.tf32.tf32.f32 "
        "{%0,%1,%2,%3}, {%4,%5,%6,%7}, {%8,%9}, {%0,%1,%2,%3};"
        : "+f"(c[0]), "+f"(c[1]), "+f"(c[2]), "+f"(c[3])
        : "r"(a[0]), "r"(a[1]), "r"(a[2]), "r"(a[3]),
          "r"(b[0]), "r"(b[1]));
}

__device__ __forceinline__ void cp_async16(float* smem, const float* gmem) {
    uint32_t s = (uint32_t)__cvta_generic_to_shared(smem);
    asm volatile("cp.async.cg.shared.global [%0], [%1], 16;"
                 :: "r"(s), "l"(gmem));
}
__device__ __forceinline__ void cp_async16_pred(float* smem, const float* gmem, bool p) {
    uint32_t s = (uint32_t)__cvta_generic_to_shared(smem);
    int sz = p ? 16 : 0;
    asm volatile("cp.async.cg.shared.global [%0], [%1], 16, %2;"
                 :: "r"(s), "l"(gmem), "r"(sz));
}
#define CP_COMMIT() asm volatile("cp.async.commit_group;")
#define CP_WAIT1()  asm volatile("cp.async.wait_group 1;")

// ---------------------------------------------------------------------------
// Weight pre-rounding to tf32 (stored as fp32 bits)
// ---------------------------------------------------------------------------
__global__ void __launch_bounds__(256) round_w_kernel(
    const float4* __restrict__ in, float4* __restrict__ out, int n4)
{
    int i = blockIdx.x * 256 + threadIdx.x;
    if (i >= n4) return;
    float4 v = __ldg(in + i);
    v.x = tf32f(v.x); v.y = tf32f(v.y); v.z = tf32f(v.z); v.w = tf32f(v.w);
    out[i] = v;
}

// ---------------------------------------------------------------------------
// TF32 tensor-core GEMM, BK=32, 2-stage cp.async pipeline, fused epilogues.
// Weights (B) MUST be pre-rounded to tf32. A must be pre-rounded unless CVTA.
// MODE: 0 = bias only; 1 = snake (+tf32 round on store); 2 = gated residual.
// ---------------------------------------------------------------------------
#define TG_SMEM ((2 * 128 * 36 + 2 * 32 * 136) * 4)

template <int MODE, bool CVTA>
__global__ void __launch_bounds__(256) tgemm_kernel(
    const float* __restrict__ A, const float* __restrict__ W,
    const float* __restrict__ bias, float* __restrict__ C,
    int M, int N, int K,
    const float* __restrict__ p1, const float* __restrict__ p2, int goff)
{
    extern __shared__ float sm[];
    float* As = sm;                  // [2][128*36]
    float* Bs = sm + 2 * 128 * 36;   // [2][32*136]

    const int bm  = blockIdx.y * 128;
    const int bn  = blockIdx.x * 128;
    const int tid = threadIdx.x;
    const int wid = tid >> 5, lane = tid & 31;
    const int g = lane >> 2, t = lane & 3;
    const int wm = (wid >> 2) * 64;
    const int wn = (wid & 3) * 32;

    const int KT = K >> 5;

    auto load_stage = [&](int s, int k0) {
        float* as = As + s * 128 * 36;
        float* bs = Bs + s * 32 * 136;
#pragma unroll
        for (int u = 0; u < 4; u++) {
            int l = tid + u * 256;
            int r = l >> 3, c = (l & 7) * 4;
            cp_async16(as + r * 36 + c, A + (size_t)(bm + r) * K + k0 + c);
        }
#pragma unroll
        for (int u = 0; u < 4; u++) {
            int l = tid + u * 256;
            int r = l >> 5, c = (l & 31) * 4;
            int col = bn + c;
            bool ok = col < N;
            cp_async16_pred(bs + r * 136 + c,
                            W + (size_t)(k0 + r) * N + (ok ? col : 0), ok);
        }
    };

    float acc[4][4][4];
#pragma unroll
    for (int mt = 0; mt < 4; mt++)
#pragma unroll
        for (int nt = 0; nt < 4; nt++)
#pragma unroll
            for (int r = 0; r < 4; r++) acc[mt][nt][r] = 0.f;

    load_stage(0, 0);
    CP_COMMIT();

    for (int ki = 0; ki < KT; ki++) {
        if (ki + 1 < KT) load_stage((ki + 1) & 1, (ki + 1) * 32);
        CP_COMMIT();
        CP_WAIT1();
        __syncthreads();

        const float* as = As + (ki & 1) * 128 * 36;
        const float* bs = Bs + (ki & 1) * 32 * 136;
#pragma unroll
        for (int ks = 0; ks < 32; ks += 8) {
            uint32_t a[4][4], b[4][2];
#pragma unroll
            for (int mt = 0; mt < 4; mt++) {
                int m0 = wm + mt * 16;
                if (CVTA) {
                    a[mt][0] = tf32u(as[(m0 + g) * 36 + ks + t]);
                    a[mt][1] = tf32u(as[(m0 + 8 + g) * 36 + ks + t]);
                    a[mt][2] = tf32u(as[(m0 + g) * 36 + ks + t + 4]);
                    a[mt][3] = tf32u(as[(m0 + 8 + g) * 36 + ks + t + 4]);
                } else {
                    a[mt][0] = __float_as_uint(as[(m0 + g) * 36 + ks + t]);
                    a[mt][1] = __float_as_uint(as[(m0 + 8 + g) * 36 + ks + t]);
                    a[mt][2] = __float_as_uint(as[(m0 + g) * 36 + ks + t + 4]);
                    a[mt][3] = __float_as_uint(as[(m0 + 8 + g) * 36 + ks + t + 4]);
                }
            }
#pragma unroll
            for (int nt = 0; nt < 4; nt++) {
                int n0 = wn + nt * 8;
                b[nt][0] = __float_as_uint(bs[(ks + t) * 136 + n0 + g]);
                b[nt][1] = __float_as_uint(bs[(ks + t + 4) * 136 + n0 + g]);
            }
#pragma unroll
            for (int mt = 0; mt < 4; mt++)
#pragma unroll
                for (int nt = 0; nt < 4; nt++)
                    mma_tf32(acc[mt][nt], a[mt], b[nt]);
        }
        __syncthreads();
    }

#pragma unroll
    for (int mt = 0; mt < 4; mt++) {
        int r0 = bm + wm + mt * 16 + g;
#pragma unroll
        for (int nt = 0; nt < 4; nt++) {
            int c0 = bn + wn + nt * 8 + 2 * t;
            if (c0 < N) {
#pragma unroll
                for (int half = 0; half < 2; half++) {
                    int rr = r0 + half * 8;
#pragma unroll
                    for (int e = 0; e < 2; e++) {
                        int cc = c0 + e;
                        float v = acc[mt][nt][half * 2 + e];
                        if (bias) v += bias[cc];
                        if (MODE == 1) {
                            float sn = __sinf(p1[cc] * v);
                            v += sn * sn / (p2[cc] + 1e-9f);
                            v = tf32f(v);      // consumer is a GEMM
                        }
                        if (MODE == 2) {
                            int bb = rr >> 10;
                            float gg = p1[bb * 6144 + goff + cc];
                            float sg = 1.f / (1.f + __expf(gg - 1.f));
                            v = C[(size_t)rr * N + cc] + v * sg;
                        }
                        C[(size_t)rr * N + cc] = v;
                    }
                }
            }
        }
    }
}

// ---------------------------------------------------------------------------
// Small-M GEMM (M=2), 64-way K split, float4 columns
// ---------------------------------------------------------------------------
__global__ void __launch_bounds__(128) gemm2_part_kernel(
    const float* __restrict__ A2, const float* __restrict__ W,
    float* __restrict__ part, int N)
{
    int n4 = N >> 2;
    int c4 = blockIdx.x * 128 + threadIdx.x;
    int kb = blockIdx.y, k0 = kb * 16;
    float4 s0 = make_float4(0.f, 0.f, 0.f, 0.f);
    float4 s1 = make_float4(0.f, 0.f, 0.f, 0.f);
    const float4* wp = (const float4*)W + (size_t)k0 * n4 + c4;
#pragma unroll 16
    for (int k = 0; k < 16; k++) {
        float4 w = __ldg(wp + (size_t)k * n4);
        float x0 = __ldg(A2 + k0 + k);
        float x1 = __ldg(A2 + 1024 + k0 + k);
        s0.x += x0 * w.x; s0.y += x0 * w.y; s0.z += x0 * w.z; s0.w += x0 * w.w;
        s1.x += x1 * w.x; s1.y += x1 * w.y; s1.z += x1 * w.z; s1.w += x1 * w.w;
    }
    ((float4*)part)[(size_t)(kb * 2 + 0) * n4 + c4] = s0;
    ((float4*)part)[(size_t)(kb * 2 + 1) * n4 + c4] = s1;
}

__global__ void __launch_bounds__(256) gemm2_reduce_kernel(
    const float* __restrict__ part, const float* __restrict__ bias,
    float* __restrict__ out, int N)
{
    int n4 = N >> 2;
    int i = blockIdx.x * 256 + threadIdx.x;
    if (i >= 2 * n4) return;
    int row = (i >= n4) ? 1 : 0;
    int c4 = i - row * n4;
    float4 s = ((const float4*)bias)[c4];
#pragma unroll 16
    for (int kb = 0; kb < 64; kb++) {
        float4 p = ((const float4*)part)[(size_t)(kb * 2 + row) * n4 + c4];
        s.x += p.x; s.y += p.y; s.z += p.z; s.w += p.w;
    }
    ((float4*)out)[(size_t)row * n4 + c4] = s;
}

// ---------------------------------------------------------------------------
// LayerNorm (+ optional affine) + adaLN modulate; output tf32-rounded iff RND
// ---------------------------------------------------------------------------
template <bool AFF, bool RND>
__global__ void __launch_bounds__(256) ln_mod_kernel(
    const float* __restrict__ x, const float* __restrict__ w,
    const float* __restrict__ bvec, const float* __restrict__ mods,
    int mstride, int sc_off, int sh_off, float eps, float* __restrict__ out)
{
    __shared__ float red[8];
    const int t = blockIdx.x;
    const int bb = t >> 10;
    const int tid = threadIdx.x;
    const float* xr = x + (size_t)t * EDIM;

    float v[4];
    float s = 0.f;
#pragma unroll
    for (int i = 0; i < 4; i++) { v[i] = xr[tid + 256 * i]; s += v[i]; }
    s = warp_sum(s);
    if ((tid & 31) == 0) red[tid >> 5] = s;
    __syncthreads();
    float tot = 0.f;
#pragma unroll
    for (int i = 0; i < 8; i++) tot += red[i];
    float mean = tot * (1.f / 1024.f);
    __syncthreads();

    float q = 0.f;
#pragma unroll
    for (int i = 0; i < 4; i++) { float d = v[i] - mean; q += d * d; }
    q = warp_sum(q);
    if ((tid & 31) == 0) red[tid >> 5] = q;
    __syncthreads();
    float vq = 0.f;
#pragma unroll
    for (int i = 0; i < 8; i++) vq += red[i];
    float inv = rsqrtf(vq * (1.f / 1024.f) + eps);

#pragma unroll
    for (int i = 0; i < 4; i++) {
        int c = tid + 256 * i;
        float y = (v[i] - mean) * inv;
        if (AFF) y = y * w[c] + bvec[c];
        y = y * (1.f + mods[bb * mstride + sc_off + c]) + mods[bb * mstride + sh_off + c];
        if (RND) y = tf32f(y);
        out[(size_t)t * EDIM + c] = y;
    }
}

// ---------------------------------------------------------------------------
// Rotary in place on q,k
// ---------------------------------------------------------------------------
__global__ void __launch_bounds__(256) rotary_kernel(float* __restrict__ qkv)
{
    int idx = blockIdx.x * 256 + threadIdx.x;
    if (idx >= NTOK * 256) return;
    int t  = idx >> 8;
    int hh = (idx >> 4) & 15;
    int j  = idx & 15;
    int s  = t & (SLEN - 1);
    float inv = exp2f(-(float)(2 * j) * (13.2877123795494f / 32.f));
    float f = (float)s * inv;
    float sf, cf;
    sincosf(f, &sf, &cf);
    float* qp = qkv + (size_t)t * 3072 + hh * 64 + 2 * j;
    float x1 = qp[0], x2 = qp[1];
    qp[0] = x1 * cf - x2 * sf;
    qp[1] = x2 * cf + x1 * sf;
    float* kp = qp + 1024;
    x1 = kp[0]; x2 = kp[1];
    kp[0] = x1 * cf - x2 * sf;
    kp[1] = x2 * cf + x1 * sf;
}

// ---------------------------------------------------------------------------
// Tensor-core flash attention (tf32 mma, causal, online softmax).
// ---------------------------------------------------------------------------
#define FT_SMEM ((64*68 + 64*68 + 64*136 + 64*68) * 4)

__global__ void __launch_bounds__(128) flash_tc_kernel(
    const float* __restrict__ qkv, float* __restrict__ a1, float* __restrict__ a2)
{
    extern __shared__ float sm[];
    float* Qs = sm;              // [64][68]
    float* Ks = Qs + 64 * 68;    // [64][68]
    float* Vs = Ks + 64 * 68;    // [64][136]
    float* Ps = Vs + 64 * 136;   // [64][68]

    const int it  = (int)gridDim.x - 1 - (int)blockIdx.x;
    const int h16 = blockIdx.y;
    const int b   = blockIdx.z;
    const int h   = h16 >> 1;
    const int tid = threadIdx.x;
    const int wid = tid >> 5, lane = tid & 31;
    const int g = lane >> 2, t = lane & 3;
    const int i0 = it * 64;
    const int m0 = wid * 16;

    const float* qb = qkv + (size_t)b * SLEN * 3072 + h16 * 64;
    const float* kb = qb + 1024;
    const float* vb = qkv + (size_t)b * SLEN * 3072 + 2048 + h * 128;
    float* ob = ((h16 & 1) ? a2 : a1) + (size_t)b * SLEN * EDIM + h * 128;

    for (int l = tid; l < 64 * 16; l += 128) {
        int r = l >> 4, c = (l & 15) << 2;
        float4 v = *(const float4*)(qb + (size_t)(i0 + r) * 3072 + c);
        float* p = Qs + r * 68 + c;
        p[0] = tf32f(v.x); p[1] = tf32f(v.y); p[2] = tf32f(v.z); p[3] = tf32f(v.w);
    }

    float mrow0 = -1e30f, mrow1 = -1e30f, lrow0 = 0.f, lrow1 = 0.f;
    float oacc[16][4];
#pragma unroll
    for (int nt = 0; nt < 16; nt++)
#pragma unroll
        for (int r = 0; r < 4; r++) oacc[nt][r] = 0.f;

    __syncthreads();

    for (int jt = 0; jt <= it; jt++) {
        int j0 = jt * 64;
        for (int l = tid; l < 64 * 16; l += 128) {
            int r = l >> 4, c = (l & 15) << 2;
            float4 v = *(const float4*)(kb + (size_t)(j0 + r) * 3072 + c);
            float* p = Ks + r * 68 + c;
            p[0] = tf32f(v.x); p[1] = tf32f(v.y); p[2] = tf32f(v.z); p[3] = tf32f(v.w);
        }
        for (int l = tid; l < 64 * 32; l += 128) {
            int r = l >> 5, c = (l & 31) << 2;
            float4 v = *(const float4*)(vb + (size_t)(j0 + r) * 3072 + c);
            float* p = Vs + r * 136 + c;
            p[0] = tf32f(v.x); p[1] = tf32f(v.y); p[2] = tf32f(v.z); p[3] = tf32f(v.w);
        }
        __syncthreads();

        float sacc[8][4];
#pragma unroll
        for (int nt = 0; nt < 8; nt++)
#pragma unroll
            for (int r = 0; r < 4; r++) sacc[nt][r] = 0.f;

#pragma unroll
        for (int ks = 0; ks < 64; ks += 8) {
            uint32_t af[4];
            af[0] = __float_as_uint(Qs[(m0 + g) * 68 + ks + t]);
            af[1] = __float_as_uint(Qs[(m0 + 8 + g) * 68 + ks + t]);
            af[2] = __float_as_uint(Qs[(m0 + g) * 68 + ks + t + 4]);
            af[3] = __float_as_uint(Qs[(m0 + 8 + g) * 68 + ks + t + 4]);
#pragma unroll
            for (int nt = 0; nt < 8; nt++) {
                uint32_t bf[2];
                bf[0] = __float_as_uint(Ks[(nt * 8 + g) * 68 + ks + t]);
                bf[1] = __float_as_uint(Ks[(nt * 8 + g) * 68 + ks + t + 4]);
                mma_tf32(sacc[nt], af, bf);
            }
        }

        const int row0 = i0 + m0 + g, row1 = row0 + 8;
        float tm0 = -1e30f, tm1 = -1e30f;
#pragma unroll
        for (int nt = 0; nt < 8; nt++) {
            int c0 = j0 + nt * 8 + 2 * t;
            sacc[nt][0] = (c0     <= row0) ? sacc[nt][0] * 0.125f : -1e30f;
            sacc[nt][1] = (c0 + 1 <= row0) ? sacc[nt][1] * 0.125f : -1e30f;
            sacc[nt][2] = (c0     <= row1) ? sacc[nt][2] * 0.125f : -1e30f;
            sacc[nt][3] = (c0 + 1 <= row1) ? sacc[nt][3] * 0.125f : -1e30f;
            tm0 = fmaxf(tm0, fmaxf(sacc[nt][0], sacc[nt][1]));
            tm1 = fmaxf(tm1, fmaxf(sacc[nt][2], sacc[nt][3]));
        }
        tm0 = fmaxf(tm0, __shfl_xor_sync(0xffffffffu, tm0, 1));
        tm0 = fmaxf(tm0, __shfl_xor_sync(0xffffffffu, tm0, 2));
        tm1 = fmaxf(tm1, __shfl_xor_sync(0xffffffffu, tm1, 1));
        tm1 = fmaxf(tm1, __shfl_xor_sync(0xffffffffu, tm1, 2));

        float nm0 = fmaxf(mrow0, tm0), nm1 = fmaxf(mrow1, tm1);
        float f0 = __expf(mrow0 - nm0), f1 = __expf(mrow1 - nm1);
        mrow0 = nm0; mrow1 = nm1;

        float ts0 = 0.f, ts1 = 0.f;
#pragma unroll
        for (int nt = 0; nt < 8; nt++) {
            float p00 = tf32f(__expf(sacc[nt][0] - nm0));
            float p01 = tf32f(__expf(sacc[nt][1] - nm0));
            float p10 = tf32f(__expf(sacc[nt][2] - nm1));
            float p11 = tf32f(__expf(sacc[nt][3] - nm1));
            ts0 += p00 + p01; ts1 += p10 + p11;
            float* pr0 = Ps + (m0 + g) * 68 + nt * 8 + 2 * t;
            float* pr1 = Ps + (m0 + 8 + g) * 68 + nt * 8 + 2 * t;
            pr0[0] = p00; pr0[1] = p01;
            pr1[0] = p10; pr1[1] = p11;
        }
        ts0 += __shfl_xor_sync(0xffffffffu, ts0, 1);
        ts0 += __shfl_xor_sync(0xffffffffu, ts0, 2);
        ts1 += __shfl_xor_sync(0xffffffffu, ts1, 1);
        ts1 += __shfl_xor_sync(0xffffffffu, ts1, 2);
        lrow0 = lrow0 * f0 + ts0;
        lrow1 = lrow1 * f1 + ts1;

#pragma unroll
        for (int nt = 0; nt < 16; nt++) {
            oacc[nt][0] *= f0; oacc[nt][1] *= f0;
            oacc[nt][2] *= f1; oacc[nt][3] *= f1;
        }
        __syncwarp();

#pragma unroll
        for (int ks = 0; ks < 64; ks += 8) {
            uint32_t af[4];
            af[0] = __float_as_uint(Ps[(m0 + g) * 68 + ks + t]);
            af[1] = __float_as_uint(Ps[(m0 + 8 + g) * 68 + ks + t]);
            af[2] = __float_as_uint(Ps[(m0 + g) * 68 + ks + t + 4]);
            af[3] = __float_as_uint(Ps[(m0 + 8 + g) * 68 + ks + t + 4]);
#pragma unroll
            for (int nt = 0; nt < 16; nt++) {
                uint32_t bf[2];
                bf[0] = __float_as_uint(Vs[(ks + t) * 136 + nt * 8 + g]);
                bf[1] = __float_as_uint(Vs[(ks + t + 4) * 136 + nt * 8 + g]);
                mma_tf32(oacc[nt], af, bf);
            }
        }
        __syncthreads();
    }

    float inv0 = 1.f / lrow0, inv1 = 1.f / lrow1;
#pragma unroll
    for (int nt = 0; nt < 16; nt++) {
        int c0 = nt * 8 + 2 * t;
        *(float2*)(ob + (size_t)(i0 + m0 + g) * EDIM + c0) =
            make_float2(oacc[nt][0] * inv0, oacc[nt][1] * inv0);
        *(float2*)(ob + (size_t)(i0 + m0 + 8 + g) * EDIM + c0) =
            make_float2(oacc[nt][2] * inv1, oacc[nt][3] * inv1);
    }
}

// ---------------------------------------------------------------------------
// Lambda scalar
// ---------------------------------------------------------------------------
__global__ void lambda_kernel(const float* __restrict__ lq1, const float* __restrict__ lk1,
                              const float* __restrict__ lq2, const float* __restrict__ lk2,
                              float lam_init, float* __restrict__ out)
{
    int tid = threadIdx.x;
    float s1 = lq1[tid] * lk1[tid] + lq1[tid + 32] * lk1[tid + 32];
    float s2 = lq2[tid] * lk2[tid] + lq2[tid + 32] * lk2[tid + 32];
    s1 = warp_sum(s1);
    s2 = warp_sum(s2);
    if (tid == 0) out[0] = expf(s1) - expf(s2) + lam_init;
}

// ---------------------------------------------------------------------------
// RMS-norm of (a1 - lam*a2) per head dim 128; output tf32-rounded (feeds GEMM)
// ---------------------------------------------------------------------------
__global__ void __launch_bounds__(128) rmsdiff_kernel(
    const float* __restrict__ a1, const float* __restrict__ a2,
    const float* __restrict__ w, const float* __restrict__ bvec,
    const float* __restrict__ lamp, float oml, float* __restrict__ out)
{
    __shared__ float red[4];
    int blk = blockIdx.x;
    int tok = blk >> 3, hh = blk & 7;
    int c = threadIdx.x;
    size_t base = (size_t)tok * EDIM + hh * 128 + c;
    float lam = lamp[0];
    float y = a1[base] - lam * a2[base];
    float q = warp_sum(y * y);
    if ((c & 31) == 0) red[c >> 5] = q;
    __syncthreads();
    float tot = red[0] + red[1] + red[2] + red[3];
    float inv = rsqrtf(tot * (1.f / 128.f) + 1e-8f);
    out[base] = tf32f((y * inv * w[c] + bvec[c]) * oml);
}

// ---------------------------------------------------------------------------
// Launch
// ---------------------------------------------------------------------------
extern "C" void kernel_launch(void* const* d_in, const int* in_sizes, int n_in,
                              void* d_out, int out_size)
{
    const float* x        = (const float*)d_in[0];
    const float* emb      = (const float*)d_in[1];
    const float* l2e_w1   = (const float*)d_in[2];
    const float* l2e_b1   = (const float*)d_in[3];
    const float* l2e_al   = (const float*)d_in[4];
    const float* l2e_be   = (const float*)d_in[5];
    const float* l2e_w2   = (const float*)d_in[6];
    const float* l2e_b2   = (const float*)d_in[7];
    const float* ln1_w    = (const float*)d_in[8];
    const float* ln1_b    = (const float*)d_in[9];
    const float* ln2_w    = (const float*)d_in[10];
    const float* ln2_b    = (const float*)d_in[11];
    const float* qkv_w    = (const float*)d_in[12];
    const float* out_w    = (const float*)d_in[13];
    const float* lq1      = (const float*)d_in[14];
    const float* lk1      = (const float*)d_in[15];
    const float* lq2      = (const float*)d_in[16];
    const float* lk2      = (const float*)d_in[17];
    const float* aln_w    = (const float*)d_in[18];
    const float* aln_b    = (const float*)d_in[19];
    const float* ada_w    = (const float*)d_in[20];
    const float* ada_b    = (const float*)d_in[21];
    const float* ff_w1    = (const float*)d_in[22];
    const float* ff_b1    = (const float*)d_in[23];
    const float* ff_al    = (const float*)d_in[24];
    const float* ff_be    = (const float*)d_in[25];
    const float* ff_w2    = (const float*)d_in[26];
    const float* ff_b2    = (const float*)d_in[27];
    const float* adaf_w   = (const float*)d_in[28];
    const float* adaf_b   = (const float*)d_in[29];
    const float* fin_w    = (const float*)d_in[30];
    const float* fin_b    = (const float*)d_in[31];

    float *h_, *t_, *qkv_, *a1_, *a2_, *hid_, *mods_, *fmods_, *lam_, *part_;
    float *w_l2e1, *w_l2e2, *w_qkv, *w_out, *w_ff1, *w_ff2, *w_fin;
    cudaGetSymbolAddress((void**)&h_,    g_h);
    cudaGetSymbolAddress((void**)&t_,    g_t);
    cudaGetSymbolAddress((void**)&qkv_,  g_qkv);
    cudaGetSymbolAddress((void**)&a1_,   g_a1);
    cudaGetSymbolAddress((void**)&a2_,   g_a2);
    cudaGetSymbolAddress((void**)&hid_,  g_hid);
    cudaGetSymbolAddress((void**)&mods_, g_mods);
    cudaGetSymbolAddress((void**)&fmods_,g_fmods);
    cudaGetSymbolAddress((void**)&lam_,  g_lam);
    cudaGetSymbolAddress((void**)&part_, g_part);
    cudaGetSymbolAddress((void**)&w_l2e1, g_w_l2e1);
    cudaGetSymbolAddress((void**)&w_l2e2, g_w_l2e2);
    cudaGetSymbolAddress((void**)&w_qkv,  g_w_qkv);
    cudaGetSymbolAddress((void**)&w_out,  g_w_out);
    cudaGetSymbolAddress((void**)&w_ff1,  g_w_ff1);
    cudaGetSymbolAddress((void**)&w_ff2,  g_w_ff2);
    cudaGetSymbolAddress((void**)&w_fin,  g_w_fin);

    cudaFuncSetAttribute(flash_tc_kernel, cudaFuncAttributeMaxDynamicSharedMemorySize,
                         FT_SMEM);
    cudaFuncSetAttribute(tgemm_kernel<0, false>, cudaFuncAttributeMaxDynamicSharedMemorySize, TG_SMEM);
    cudaFuncSetAttribute(tgemm_kernel<1, false>, cudaFuncAttributeMaxDynamicSharedMemorySize, TG_SMEM);
    cudaFuncSetAttribute(tgemm_kernel<2, false>, cudaFuncAttributeMaxDynamicSharedMemorySize, TG_SMEM);
    cudaFuncSetAttribute(tgemm_kernel<1, true>,  cudaFuncAttributeMaxDynamicSharedMemorySize, TG_SMEM);

    // ---- pre-round all weights to tf32 ----
    auto roundw = [&](const float* in, float* out, size_t n) {
        int n4 = (int)(n >> 2);
        round_w_kernel<<<(n4 + 255) / 256, 256>>>((const float4*)in, (float4*)out, n4);
    };
    roundw(l2e_w1, w_l2e1, (size_t)64 * EDIM);
    roundw(l2e_w2, w_l2e2, (size_t)EDIM * EDIM);
    roundw(qkv_w,  w_qkv,  (size_t)NB * EDIM * 3 * EDIM);
    roundw(out_w,  w_out,  (size_t)NB * EDIM * EDIM);
    roundw(ff_w1,  w_ff1,  (size_t)NB * EDIM * E4DIM);
    roundw(ff_w2,  w_ff2,  (size_t)NB * E4DIM * EDIM);
    roundw(fin_w,  w_fin,  (size_t)EDIM * 64);

    auto gemmN = [&](const float* A, const float* W, const float* bias, float* C,
                     int M, int N, int K) {
        dim3 grid((N + 127) / 128, M / 128);
        tgemm_kernel<0, false><<<grid, 256, TG_SMEM>>>(A, W, bias, C, M, N, K,
                                                       nullptr, nullptr, 0);
    };
    auto gemmS = [&](const float* A, const float* W, const float* bias, float* C,
                     int M, int N, int K, const float* al, const float* be, bool cvta) {
        dim3 grid((N + 127) / 128, M / 128);
        if (cvta)
            tgemm_kernel<1, true><<<grid, 256, TG_SMEM>>>(A, W, bias, C, M, N, K, al, be, 0);
        else
            tgemm_kernel<1, false><<<grid, 256, TG_SMEM>>>(A, W, bias, C, M, N, K, al, be, 0);
    };
    auto gemmG = [&](const float* A, const float* W, const float* bias, float* C,
                     int M, int N, int K, const float* mods, int goff) {
        dim3 grid((N + 127) / 128, M / 128);
        tgemm_kernel<2, false><<<grid, 256, TG_SMEM>>>(A, W, bias, C, M, N, K,
                                                       mods, nullptr, goff);
    };
    auto gemm2 = [&](const float* W, const float* bias, float* out, int N) {
        gemm2_part_kernel<<<dim3(N / 512, 64), 128>>>(emb, W, part_, N);
        gemm2_reduce_kernel<<<(2 * (N / 4) + 255) / 256, 256>>>(part_, bias, out, N);
    };

    // latent -> embedding (snake fused; A = raw x so CVTA)
    gemmS(x, w_l2e1, l2e_b1, t_, NTOK, EDIM, 64, l2e_al, l2e_be, true);
    gemmN(t_, w_l2e2, l2e_b2, h_, NTOK, EDIM, EDIM);

    for (int i = 0; i < NB; i++) {
        float lam_init = (float)(0.8 - 0.6 * exp(-0.3 * (double)(i + 1)));

        gemm2(ada_w + (size_t)i * EDIM * 6144, ada_b + i * 6144, mods_, 6144);
        lambda_kernel<<<1, 32>>>(lq1 + i * 64, lk1 + i * 64, lq2 + i * 64, lk2 + i * 64,
                                 lam_init, lam_);

        // attention half
        ln_mod_kernel<true, true><<<NTOK, 256>>>(h_, ln1_w + i * EDIM, ln1_b + i * EDIM,
                                                 mods_, 6144, 0, 1024, 1e-5f, t_);
        gemmN(t_, w_qkv + (size_t)i * EDIM * 3072, nullptr, qkv_, NTOK, 3072, EDIM);
        rotary_kernel<<<NTOK, 256>>>(qkv_);
        flash_tc_kernel<<<dim3(16, 16, 2), 128, FT_SMEM>>>(qkv_, a1_, a2_);
        rmsdiff_kernel<<<NTOK * 8, 128>>>(a1_, a2_, aln_w + i * 128, aln_b + i * 128,
                                          lam_, 1.f - lam_init, t_);
        gemmG(t_, w_out + (size_t)i * EDIM * EDIM, nullptr, h_, NTOK, EDIM, EDIM,
              mods_, 4096);

        // MLP half
        ln_mod_kernel<true, true><<<NTOK, 256>>>(h_, ln2_w + i * EDIM, ln2_b + i * EDIM,
                                                 mods_, 6144, 2048, 3072, 1e-5f, t_);
        gemmS(t_, w_ff1 + (size_t)i * EDIM * E4DIM, ff_b1 + i * E4DIM, hid_,
              NTOK, E4DIM, EDIM, ff_al + i * E4DIM, ff_be + i * E4DIM, false);
        gemmG(hid_, w_ff2 + (size_t)i * E4DIM * EDIM, ff_b2 + i * EDIM, h_,
              NTOK, EDIM, E4DIM, mods_, 5120);
    }

    // final adaLN + projection
    gemm2(adaf_w, adaf_b, fmods_, 2048);
    ln_mod_kernel<false, true><<<NTOK, 256>>>(h_, nullptr, nullptr, fmods_, 2048,
                                              0, 1024, 1e-6f, t_);
    gemmN(t_, w_fin, fin_b, (float*)d_out, NTOK, 64, EDIM);
}